// round 2
// baseline (speedup 1.0000x reference)
#include <cuda_runtime.h>
#include <cstddef>

// ---------------- problem constants ----------------
constexpr int N_  = 131072;   // inner nodes
constexpr int G_  = 2048;     // graphs / outer nodes
constexpr int E_  = 1048576;  // inner edges
constexpr int EF_ = 32768;    // outer edges
constexpr int D_  = 128;      // feature dim
constexpr int K_  = 8;        // sortpool k

// ---------------- scratch (static device globals; no allocation) ----------------
__device__ float d_gx[(size_t)N_ * D_];   // node features (current)
__device__ float d_gf[(size_t)N_ * D_];   // projected features f = x @ W
__device__ float d_go[(size_t)N_ * D_];   // aggregation output
__device__ float d_gel[N_];
__device__ float d_ger[N_];
__device__ float d_gs[N_];
__device__ float d_gea[E_];
__device__ float d_pool[(size_t)G_ * K_ * D_];   // [2048, 1024]
__device__ float d_hf[G_ * D_];
__device__ float d_ho[G_ * D_];
__device__ float d_hx[G_ * D_];
__device__ float d_hy[G_ * D_];
__device__ float d_hel[G_];
__device__ float d_her[G_];
__device__ float d_hs[G_];
__device__ float d_hea[EF_];

// ---------------- utility kernels ----------------
__global__ void zero_kernel(float* __restrict__ p, int n) {
    int i = blockIdx.x * blockDim.x + threadIdx.x;
    int stride = gridDim.x * blockDim.x;
    for (; i < n; i += stride) p[i] = 0.f;
}

__global__ void embed_relu_kernel(const int* __restrict__ h,
                                  const float* __restrict__ emb,
                                  float* __restrict__ x, int total) {
    int i = blockIdx.x * blockDim.x + threadIdx.x;
    if (i >= total) return;
    int node = i >> 7;
    int c = i & 127;
    x[i] = fmaxf(emb[h[node] * D_ + c], 0.f);
}

__global__ void bias_relu_kernel(const float* __restrict__ in,
                                 const float* __restrict__ b,
                                 float* __restrict__ out, int total) {
    int i = blockIdx.x * blockDim.x + threadIdx.x;
    if (i >= total) return;
    out[i] = fmaxf(in[i] + b[i & 127], 0.f);
}

// ---------------- GEMM: C[M,128] = act(A[M,K] @ B[K,128] (+bias)),
// optional fused attention dots el = row . al, er = row . ar ----------------
template <int BM, int TM, int TN, bool HASBIAS, bool RELU, bool DOTS>
__global__ void gemm_kernel(const float* __restrict__ A,
                            const float* __restrict__ B,
                            const float* __restrict__ bias,
                            const float* __restrict__ al,
                            const float* __restrict__ ar,
                            float* __restrict__ C,
                            float* __restrict__ el,
                            float* __restrict__ er,
                            int M, int K) {
    constexpr int BN = 128;
    constexpr int BK = 16;
    constexpr int TX = BN / TN;
    constexpr int TY = BM / TM;
    constexpr int NT = TX * TY;   // block size
    static_assert(NT == 256, "block must be 256 threads");

    __shared__ float As[BK][BM];
    __shared__ float Bs[BK][BN];

    int t  = threadIdx.x;
    int tx = t % TX;
    int ty = t / TX;
    int m0 = blockIdx.x * BM;

    float acc[TM][TN];
#pragma unroll
    for (int i = 0; i < TM; i++)
#pragma unroll
        for (int j = 0; j < TN; j++) acc[i][j] = 0.f;

    for (int k0 = 0; k0 < K; k0 += BK) {
        // load A tile (BM x BK)
#pragma unroll
        for (int idx = t; idx < BM * BK; idx += NT) {
            int m = idx / BK;
            int k = idx % BK;
            As[k][m] = A[(size_t)(m0 + m) * K + (k0 + k)];
        }
        // load B tile (BK x BN)
#pragma unroll
        for (int idx = t; idx < BK * BN; idx += NT) {
            int k = idx / BN;
            int n = idx % BN;
            Bs[k][n] = B[(size_t)(k0 + k) * BN + n];
        }
        __syncthreads();
#pragma unroll
        for (int k = 0; k < BK; k++) {
            float a[TM], b[TN];
#pragma unroll
            for (int i = 0; i < TM; i++) a[i] = As[k][ty * TM + i];
#pragma unroll
            for (int j = 0; j < TN; j++) b[j] = Bs[k][tx * TN + j];
#pragma unroll
            for (int i = 0; i < TM; i++)
#pragma unroll
                for (int j = 0; j < TN; j++) acc[i][j] += a[i] * b[j];
        }
        __syncthreads();
    }

    // epilogue: store C (with optional bias/relu)
#pragma unroll
    for (int i = 0; i < TM; i++) {
        int m = m0 + ty * TM + i;
#pragma unroll
        for (int j = 0; j < TN; j++) {
            int nn = tx * TN + j;
            float v = acc[i][j];
            if (HASBIAS) v += bias[nn];
            if (RELU) v = fmaxf(v, 0.f);
            C[(size_t)m * BN + nn] = v;
        }
    }

    if constexpr (DOTS) {
        float alv[TN], arv[TN];
#pragma unroll
        for (int j = 0; j < TN; j++) {
            int nn = tx * TN + j;
            alv[j] = al[nn];
            arv[j] = ar[nn];
        }
#pragma unroll
        for (int i = 0; i < TM; i++) {
            float pl = 0.f, pr = 0.f;
#pragma unroll
            for (int j = 0; j < TN; j++) {
                pl += acc[i][j] * alv[j];
                pr += acc[i][j] * arv[j];
            }
#pragma unroll
            for (int o = TX / 2; o > 0; o >>= 1) {
                pl += __shfl_xor_sync(0xffffffffu, pl, o);
                pr += __shfl_xor_sync(0xffffffffu, pr, o);
            }
            if (tx == 0) {
                int m = m0 + ty * TM + i;
                el[m] = pl;
                er[m] = pr;
            }
        }
    }
}

// ---------------- edge kernels ----------------
// pass 1: a_e = exp(leaky_relu(el[src]+er[dst])); ssum[dst] += a_e
__global__ void edge_softmax_kernel(const int* __restrict__ src,
                                    const int* __restrict__ dst,
                                    const float* __restrict__ el,
                                    const float* __restrict__ er,
                                    float* __restrict__ ea,
                                    float* __restrict__ ssum, int nE) {
    int e = blockIdx.x * blockDim.x + threadIdx.x;
    if (e >= nE) return;
    float v = el[src[e]] + er[dst[e]];
    v = v > 0.f ? v : 0.2f * v;
    float a = expf(v);
    ea[e] = a;
    atomicAdd(&ssum[dst[e]], a);
}

// pass 2: out[dst] += (a_e / ssum[dst]) * f[src]   (warp per edge, float4 lanes)
__global__ void edge_aggregate_kernel(const int* __restrict__ src,
                                      const int* __restrict__ dst,
                                      const float* __restrict__ ea,
                                      const float* __restrict__ ssum,
                                      const float* __restrict__ f,
                                      float* __restrict__ out, int nE) {
    int e = (blockIdx.x * blockDim.x + threadIdx.x) >> 5;
    int lane = threadIdx.x & 31;
    if (e >= nE) return;
    int s = src[e];
    int d = dst[e];
    float coef = ea[e] / ssum[d];
    float4 v = reinterpret_cast<const float4*>(f + (size_t)s * D_)[lane];
    float* orow = out + (size_t)d * D_ + lane * 4;
    atomicAdd(orow + 0, coef * v.x);
    atomicAdd(orow + 1, coef * v.y);
    atomicAdd(orow + 2, coef * v.z);
    atomicAdd(orow + 3, coef * v.w);
}

// ---------------- SortPooling ----------------
// Per graph (64 nodes): rank nodes by per-node max (desc, stable ties by index),
// take top-8, sort each selected node's 128 features ascending, concat.
__global__ void sortpool_kernel(const float* __restrict__ x, float* __restrict__ y) {
    int g = blockIdx.x;
    __shared__ float mx[64];
    __shared__ int sel[8];
    __shared__ float buf[8][128];
    int t = threadIdx.x;
    int w = t >> 5;
    int lane = t & 31;
    const float* xg = x + (size_t)g * 64 * D_;

    // per-node max (8 warps x 8 nodes)
#pragma unroll
    for (int it = 0; it < 8; it++) {
        int j = w * 8 + it;
        float4 v = reinterpret_cast<const float4*>(xg + (size_t)j * D_)[lane];
        float m = fmaxf(fmaxf(v.x, v.y), fmaxf(v.z, v.w));
#pragma unroll
        for (int o = 16; o > 0; o >>= 1)
            m = fmaxf(m, __shfl_xor_sync(0xffffffffu, m, o));
        if (lane == 0) mx[j] = m;
    }
    __syncthreads();

    // rank (stable: desc by value, ties by smaller index first)
    if (t < 64) {
        float mj = mx[t];
        int rank = 0;
        for (int i = 0; i < 64; i++) {
            float mi = mx[i];
            rank += (mi > mj) || (mi == mj && i < t);
        }
        if (rank < 8) sel[rank] = t;
    }
    __syncthreads();

    // warp w sorts node sel[w]'s 128 features ascending (bitonic in smem)
    int j = sel[w];
    reinterpret_cast<float4*>(buf[w])[lane] =
        reinterpret_cast<const float4*>(xg + (size_t)j * D_)[lane];
    __syncwarp();
    for (int k2 = 2; k2 <= 128; k2 <<= 1) {
        for (int jj = k2 >> 1; jj > 0; jj >>= 1) {
#pragma unroll
            for (int base = 0; base < 128; base += 32) {
                int i = base + lane;
                int p = i ^ jj;
                if (p > i) {
                    float a = buf[w][i];
                    float b = buf[w][p];
                    bool up = (i & k2) == 0;
                    if ((a > b) == up) {
                        buf[w][i] = b;
                        buf[w][p] = a;
                    }
                }
            }
            __syncwarp();
        }
    }
    reinterpret_cast<float4*>(y + (size_t)g * (K_ * D_) + w * D_)[lane] =
        reinterpret_cast<float4*>(buf[w])[lane];
}

// ---------------- classifier: out[G,2] = x @ Wc + bc (warp per row) ----------------
__global__ void classifier_kernel(const float* __restrict__ x,
                                  const float* __restrict__ Wc,
                                  const float* __restrict__ bc,
                                  float* __restrict__ out) {
    int row = (blockIdx.x * blockDim.x + threadIdx.x) >> 5;
    int lane = threadIdx.x & 31;
    if (row >= G_) return;
    float4 v = reinterpret_cast<const float4*>(x + (size_t)row * D_)[lane];
    int k = lane * 4;
    float a0 = v.x * Wc[(k + 0) * 2 + 0] + v.y * Wc[(k + 1) * 2 + 0] +
               v.z * Wc[(k + 2) * 2 + 0] + v.w * Wc[(k + 3) * 2 + 0];
    float a1 = v.x * Wc[(k + 0) * 2 + 1] + v.y * Wc[(k + 1) * 2 + 1] +
               v.z * Wc[(k + 2) * 2 + 1] + v.w * Wc[(k + 3) * 2 + 1];
#pragma unroll
    for (int o = 16; o > 0; o >>= 1) {
        a0 += __shfl_xor_sync(0xffffffffu, a0, o);
        a1 += __shfl_xor_sync(0xffffffffu, a1, o);
    }
    if (lane == 0) {
        out[row * 2 + 0] = a0 + bc[0];
        out[row * 2 + 1] = a1 + bc[1];
    }
}

// ---------------- launch ----------------
extern "C" void kernel_launch(void* const* d_in, const int* in_sizes, int n_in,
                              void* d_out, int out_size) {
    const int*   h      = (const int*)d_in[0];
    const int*   gsrc   = (const int*)d_in[1];
    const int*   gdst   = (const int*)d_in[2];
    const int*   fgsrc  = (const int*)d_in[3];
    const int*   fgdst  = (const int*)d_in[4];
    const float* emb    = (const float*)d_in[5];
    const float* W1  = (const float*)d_in[6];
    const float* al1 = (const float*)d_in[7];
    const float* ar1 = (const float*)d_in[8];
    const float* b1  = (const float*)d_in[9];
    const float* W2  = (const float*)d_in[10];
    const float* al2 = (const float*)d_in[11];
    const float* ar2 = (const float*)d_in[12];
    const float* b2  = (const float*)d_in[13];
    const float* W3  = (const float*)d_in[14];
    const float* al3 = (const float*)d_in[15];
    const float* ar3 = (const float*)d_in[16];
    const float* b3  = (const float*)d_in[17];
    const float* Wf  = (const float*)d_in[18];
    const float* bf  = (const float*)d_in[19];
    const float* Wl  = (const float*)d_in[20];
    const float* bl  = (const float*)d_in[21];
    const float* Wl1 = (const float*)d_in[22];
    const float* bl1 = (const float*)d_in[23];
    const float* Wc  = (const float*)d_in[24];
    const float* bc  = (const float*)d_in[25];
    float* out = (float*)d_out;

    float *gx, *gf, *go, *gel, *ger, *gs, *gea, *pool;
    float *hf, *ho, *hx, *hy, *hel, *her, *hs, *hea;
    cudaGetSymbolAddress((void**)&gx,  d_gx);
    cudaGetSymbolAddress((void**)&gf,  d_gf);
    cudaGetSymbolAddress((void**)&go,  d_go);
    cudaGetSymbolAddress((void**)&gel, d_gel);
    cudaGetSymbolAddress((void**)&ger, d_ger);
    cudaGetSymbolAddress((void**)&gs,  d_gs);
    cudaGetSymbolAddress((void**)&gea, d_gea);
    cudaGetSymbolAddress((void**)&pool, d_pool);
    cudaGetSymbolAddress((void**)&hf,  d_hf);
    cudaGetSymbolAddress((void**)&ho,  d_ho);
    cudaGetSymbolAddress((void**)&hx,  d_hx);
    cudaGetSymbolAddress((void**)&hy,  d_hy);
    cudaGetSymbolAddress((void**)&hel, d_hel);
    cudaGetSymbolAddress((void**)&her, d_her);
    cudaGetSymbolAddress((void**)&hs,  d_hs);
    cudaGetSymbolAddress((void**)&hea, d_hea);

    const int ND = N_ * D_;
    const int GD = G_ * D_;

    // x = relu(token_emb[h])
    embed_relu_kernel<<<(ND + 255) / 256, 256>>>(h, emb, gx, ND);

    // ---- inner GATConv x2 ----
    for (int conv = 0; conv < 2; conv++) {
        const float* W  = conv == 0 ? W1 : W2;
        const float* al = conv == 0 ? al1 : al2;
        const float* ar = conv == 0 ? ar1 : ar2;
        const float* b  = conv == 0 ? b1 : b2;

        // f = x@W, fused el/er
        gemm_kernel<128, 8, 8, false, false, true><<<N_ / 128, 256>>>(
            gx, W, nullptr, al, ar, gf, gel, ger, N_, D_);
        zero_kernel<<<4096, 256>>>(gs, N_);
        zero_kernel<<<8192, 256>>>(go, ND);
        edge_softmax_kernel<<<(E_ + 255) / 256, 256>>>(gsrc, gdst, gel, ger, gea, gs, E_);
        edge_aggregate_kernel<<<(E_ * 32) / 256, 256>>>(gsrc, gdst, gea, gs, gf, go, E_);
        // x = relu(out + b)
        bias_relu_kernel<<<(ND + 255) / 256, 256>>>(go, b, gx, ND);
    }

    // linear_forward: f = relu(x @ Wf + bf)
    gemm_kernel<128, 8, 8, true, true, false><<<N_ / 128, 256>>>(
        gx, Wf, bf, nullptr, nullptr, gf, nullptr, nullptr, N_, D_);

    // sort pooling -> pool [2048, 1024]
    sortpool_kernel<<<G_, 256>>>(gf, pool);

    // ---- outer GATConv over fg ----
    gemm_kernel<16, 2, 4, false, false, true><<<G_ / 16, 256>>>(
        pool, W3, nullptr, al3, ar3, hf, hel, her, G_, K_ * D_);
    zero_kernel<<<32, 256>>>(hs, G_);
    zero_kernel<<<1024, 256>>>(ho, GD);
    edge_softmax_kernel<<<(EF_ + 255) / 256, 256>>>(fgsrc, fgdst, hel, her, hea, hs, EF_);
    edge_aggregate_kernel<<<(EF_ * 32) / 256, 256>>>(fgsrc, fgdst, hea, hs, hf, ho, EF_);
    bias_relu_kernel<<<(GD + 255) / 256, 256>>>(ho, b3, hx, GD);

    // x = relu(x @ Wl + bl); x = relu(x @ Wl1 + bl1)
    gemm_kernel<16, 2, 4, true, true, false><<<G_ / 16, 256>>>(
        hx, Wl, bl, nullptr, nullptr, hy, nullptr, nullptr, G_, D_);
    gemm_kernel<16, 2, 4, true, true, false><<<G_ / 16, 256>>>(
        hy, Wl1, bl1, nullptr, nullptr, hx, nullptr, nullptr, G_, D_);

    // classifier
    classifier_kernel<<<(G_ * 32 + 255) / 256, 256>>>(hx, Wc, bc, out);
}

// round 3
// speedup vs baseline: 1.4721x; 1.4721x over previous
#include <cuda_runtime.h>
#include <cstddef>

// ---------------- problem constants ----------------
constexpr int N_  = 131072;   // inner nodes
constexpr int G_  = 2048;     // graphs / outer nodes
constexpr int E_  = 1048576;  // inner edges
constexpr int EF_ = 32768;    // outer edges
constexpr int D_  = 128;      // feature dim
constexpr int K_  = 8;        // sortpool k

// ---------------- scratch (static device globals; no allocation) ----------------
__device__ float d_gx[(size_t)N_ * D_];   // node features (current)
__device__ float d_gf[(size_t)N_ * D_];   // projected features f = x @ W
__device__ float d_gel[N_];
__device__ float d_ger[N_];
__device__ float d_pool[(size_t)G_ * K_ * D_];   // [2048, 1024]
__device__ float d_hf[G_ * D_];
__device__ float d_hx[G_ * D_];
__device__ float d_hy[G_ * D_];
__device__ float d_hel[G_];
__device__ float d_her[G_];

// CSR scratch (inner graph)
__device__ int d_cnt[N_];
__device__ int d_rowptr[N_ + 1];
__device__ int d_cursor[N_];
__device__ int d_col[E_];
__device__ int d_bsum[256];
// CSR scratch (outer graph)
__device__ int d_cntf[G_];
__device__ int d_rowptrf[G_ + 1];
__device__ int d_cursorf[G_];
__device__ int d_colf[EF_];
__device__ int d_bsumf[256];

// ---------------- utility kernels ----------------
__global__ void zero_int_kernel(int* __restrict__ p, int n) {
    int i = blockIdx.x * blockDim.x + threadIdx.x;
    if (i < n) p[i] = 0;
}

__global__ void embed_relu_kernel(const int* __restrict__ h,
                                  const float* __restrict__ emb,
                                  float* __restrict__ x, int total) {
    int i = blockIdx.x * blockDim.x + threadIdx.x;
    if (i >= total) return;
    int node = i >> 7;
    int c = i & 127;
    x[i] = fmaxf(emb[h[node] * D_ + c], 0.f);
}

// ---------------- CSR build ----------------
__global__ void hist_kernel(const int* __restrict__ dst, int* __restrict__ cnt, int nE) {
    int e = blockIdx.x * blockDim.x + threadIdx.x;
    if (e < nE) atomicAdd(&cnt[dst[e]], 1);
}

// per-block (1024 elems) sum -> bsum
__global__ void block_reduce_kernel(const int* __restrict__ cnt, int n,
                                    int* __restrict__ bsum) {
    __shared__ int sh[256];
    int base = blockIdx.x * 1024;
    int t = threadIdx.x;
    int s = 0;
#pragma unroll
    for (int i = 0; i < 4; i++) {
        int idx = base + t * 4 + i;
        if (idx < n) s += cnt[idx];
    }
    sh[t] = s;
    __syncthreads();
    for (int o = 128; o > 0; o >>= 1) {
        if (t < o) sh[t] += sh[t + o];
        __syncthreads();
    }
    if (t == 0) bsum[blockIdx.x] = sh[0];
}

// single-block exclusive scan of bsum (nb <= 256)
__global__ void scan_small_kernel(int* __restrict__ bsum, int nb) {
    __shared__ int sh[256];
    int t = threadIdx.x;
    int orig = t < nb ? bsum[t] : 0;
    sh[t] = orig;
    __syncthreads();
    for (int o = 1; o < 256; o <<= 1) {
        int u = t >= o ? sh[t - o] : 0;
        __syncthreads();
        sh[t] += u;
        __syncthreads();
    }
    if (t < nb) bsum[t] = sh[t] - orig;   // exclusive
}

// per-block exclusive scan with block offset; emit row_ptr (and row_ptr[n])
__global__ void block_scan_kernel(const int* __restrict__ cnt, int n,
                                  const int* __restrict__ bsum,
                                  int* __restrict__ row_ptr) {
    __shared__ int sh[256];
    int base = blockIdx.x * 1024;
    int t = threadIdx.x;
    int v[4];
    int s = 0;
#pragma unroll
    for (int i = 0; i < 4; i++) {
        int idx = base + t * 4 + i;
        v[i] = idx < n ? cnt[idx] : 0;
        s += v[i];
    }
    sh[t] = s;
    __syncthreads();
    for (int o = 1; o < 256; o <<= 1) {
        int u = t >= o ? sh[t - o] : 0;
        __syncthreads();
        sh[t] += u;
        __syncthreads();
    }
    int off = bsum[blockIdx.x] + (t > 0 ? sh[t - 1] : 0);
#pragma unroll
    for (int i = 0; i < 4; i++) {
        int idx = base + t * 4 + i;
        if (idx < n) {
            row_ptr[idx] = off;
            off += v[i];
            if (idx == n - 1) row_ptr[n] = off;
        }
    }
}

__global__ void copy_int_kernel(const int* __restrict__ a, int* __restrict__ b, int n) {
    int i = blockIdx.x * blockDim.x + threadIdx.x;
    if (i < n) b[i] = a[i];
}

__global__ void scatter_kernel(const int* __restrict__ src, const int* __restrict__ dst,
                               int* __restrict__ cursor, int* __restrict__ col, int nE) {
    int e = blockIdx.x * blockDim.x + threadIdx.x;
    if (e >= nE) return;
    int pos = atomicAdd(&cursor[dst[e]], 1);
    col[pos] = src[e];
}

// ---------------- GEMM: C[M,128] = act(A[M,K] @ B[K,128] (+bias)),
// optional fused attention dots el = row . al, er = row . ar ----------------
template <int BM, int TM, int TN, bool HASBIAS, bool RELU, bool DOTS>
__global__ void gemm_kernel(const float* __restrict__ A,
                            const float* __restrict__ B,
                            const float* __restrict__ bias,
                            const float* __restrict__ al,
                            const float* __restrict__ ar,
                            float* __restrict__ C,
                            float* __restrict__ el,
                            float* __restrict__ er,
                            int M, int K) {
    constexpr int BN = 128;
    constexpr int BK = 16;
    constexpr int TX = BN / TN;
    constexpr int TY = BM / TM;
    constexpr int NT = TX * TY;   // block size
    static_assert(NT == 256, "block must be 256 threads");

    __shared__ float As[BK][BM];
    __shared__ float Bs[BK][BN];

    int t  = threadIdx.x;
    int tx = t % TX;
    int ty = t / TX;
    int m0 = blockIdx.x * BM;

    float acc[TM][TN];
#pragma unroll
    for (int i = 0; i < TM; i++)
#pragma unroll
        for (int j = 0; j < TN; j++) acc[i][j] = 0.f;

    for (int k0 = 0; k0 < K; k0 += BK) {
        // load A tile (BM x BK)
#pragma unroll
        for (int idx = t; idx < BM * BK; idx += NT) {
            int m = idx / BK;
            int k = idx % BK;
            As[k][m] = A[(size_t)(m0 + m) * K + (k0 + k)];
        }
        // load B tile (BK x BN)
#pragma unroll
        for (int idx = t; idx < BK * BN; idx += NT) {
            int k = idx / BN;
            int n = idx % BN;
            Bs[k][n] = B[(size_t)(k0 + k) * BN + n];
        }
        __syncthreads();
#pragma unroll
        for (int k = 0; k < BK; k++) {
            float a[TM], b[TN];
#pragma unroll
            for (int i = 0; i < TM; i++) a[i] = As[k][ty * TM + i];
#pragma unroll
            for (int j = 0; j < TN; j++) b[j] = Bs[k][tx * TN + j];
#pragma unroll
            for (int i = 0; i < TM; i++)
#pragma unroll
                for (int j = 0; j < TN; j++) acc[i][j] += a[i] * b[j];
        }
        __syncthreads();
    }

    // epilogue: store C (with optional bias/relu)
#pragma unroll
    for (int i = 0; i < TM; i++) {
        int m = m0 + ty * TM + i;
#pragma unroll
        for (int j = 0; j < TN; j++) {
            int nn = tx * TN + j;
            float v = acc[i][j];
            if (HASBIAS) v += bias[nn];
            if (RELU) v = fmaxf(v, 0.f);
            C[(size_t)m * BN + nn] = v;
        }
    }

    if constexpr (DOTS) {
        float alv[TN], arv[TN];
#pragma unroll
        for (int j = 0; j < TN; j++) {
            int nn = tx * TN + j;
            alv[j] = al[nn];
            arv[j] = ar[nn];
        }
#pragma unroll
        for (int i = 0; i < TM; i++) {
            float pl = 0.f, pr = 0.f;
#pragma unroll
            for (int j = 0; j < TN; j++) {
                pl += acc[i][j] * alv[j];
                pr += acc[i][j] * arv[j];
            }
#pragma unroll
            for (int o = TX / 2; o > 0; o >>= 1) {
                pl += __shfl_xor_sync(0xffffffffu, pl, o);
                pr += __shfl_xor_sync(0xffffffffu, pr, o);
            }
            if (tx == 0) {
                int m = m0 + ty * TM + i;
                el[m] = pl;
                er[m] = pr;
            }
        }
    }
}

// ---------------- fused GAT aggregation (warp per dst node, CSR) ----------------
// out[node] = relu( (sum_e a_e * f[src_e]) / (sum_e a_e) + b ),  a_e=exp(leaky(el+er))
__global__ void gat_aggregate_kernel(const int* __restrict__ row_ptr,
                                     const int* __restrict__ col,
                                     const float* __restrict__ el,
                                     const float* __restrict__ er,
                                     const float* __restrict__ f,
                                     const float* __restrict__ b,
                                     float* __restrict__ outx, int n) {
    int node = blockIdx.x * (blockDim.x >> 5) + (threadIdx.x >> 5);
    int lane = threadIdx.x & 31;
    if (node >= n) return;
    int s0 = row_ptr[node];
    int s1 = row_ptr[node + 1];
    float er_i = er[node];
    const float4* f4 = reinterpret_cast<const float4*>(f);
    float4 acc = {0.f, 0.f, 0.f, 0.f};
    float ssum = 0.f;
    for (int j = s0; j < s1; j++) {
        int s = col[j];
        float e = el[s] + er_i;
        e = e > 0.f ? e : 0.2f * e;
        float a = expf(e);
        ssum += a;
        float4 v = f4[(size_t)s * 32 + lane];
        acc.x += a * v.x;
        acc.y += a * v.y;
        acc.z += a * v.z;
        acc.w += a * v.w;
    }
    float inv = (s1 > s0) ? 1.f / ssum : 0.f;
    int k = lane * 4;
    float4 o;
    o.x = fmaxf(acc.x * inv + b[k + 0], 0.f);
    o.y = fmaxf(acc.y * inv + b[k + 1], 0.f);
    o.z = fmaxf(acc.z * inv + b[k + 2], 0.f);
    o.w = fmaxf(acc.w * inv + b[k + 3], 0.f);
    reinterpret_cast<float4*>(outx)[(size_t)node * 32 + lane] = o;
}

// ---------------- SortPooling ----------------
__global__ void sortpool_kernel(const float* __restrict__ x, float* __restrict__ y) {
    int g = blockIdx.x;
    __shared__ float mx[64];
    __shared__ int sel[8];
    __shared__ float buf[8][128];
    int t = threadIdx.x;
    int w = t >> 5;
    int lane = t & 31;
    const float* xg = x + (size_t)g * 64 * D_;

    // per-node max (8 warps x 8 nodes)
#pragma unroll
    for (int it = 0; it < 8; it++) {
        int j = w * 8 + it;
        float4 v = reinterpret_cast<const float4*>(xg + (size_t)j * D_)[lane];
        float m = fmaxf(fmaxf(v.x, v.y), fmaxf(v.z, v.w));
#pragma unroll
        for (int o = 16; o > 0; o >>= 1)
            m = fmaxf(m, __shfl_xor_sync(0xffffffffu, m, o));
        if (lane == 0) mx[j] = m;
    }
    __syncthreads();

    // rank (stable: desc by value, ties by smaller index first)
    if (t < 64) {
        float mj = mx[t];
        int rank = 0;
        for (int i = 0; i < 64; i++) {
            float mi = mx[i];
            rank += (mi > mj) || (mi == mj && i < t);
        }
        if (rank < 8) sel[rank] = t;
    }
    __syncthreads();

    // warp w sorts node sel[w]'s 128 features ascending (bitonic in smem)
    int j = sel[w];
    reinterpret_cast<float4*>(buf[w])[lane] =
        reinterpret_cast<const float4*>(xg + (size_t)j * D_)[lane];
    __syncwarp();
    for (int k2 = 2; k2 <= 128; k2 <<= 1) {
        for (int jj = k2 >> 1; jj > 0; jj >>= 1) {
#pragma unroll
            for (int base = 0; base < 128; base += 32) {
                int i = base + lane;
                int p = i ^ jj;
                if (p > i) {
                    float a = buf[w][i];
                    float bb = buf[w][p];
                    bool up = (i & k2) == 0;
                    if ((a > bb) == up) {
                        buf[w][i] = bb;
                        buf[w][p] = a;
                    }
                }
            }
            __syncwarp();
        }
    }
    reinterpret_cast<float4*>(y + (size_t)g * (K_ * D_) + w * D_)[lane] =
        reinterpret_cast<float4*>(buf[w])[lane];
}

// ---------------- classifier: out[G,2] = x @ Wc + bc (warp per row) ----------------
__global__ void classifier_kernel(const float* __restrict__ x,
                                  const float* __restrict__ Wc,
                                  const float* __restrict__ bc,
                                  float* __restrict__ out) {
    int row = (blockIdx.x * blockDim.x + threadIdx.x) >> 5;
    int lane = threadIdx.x & 31;
    if (row >= G_) return;
    float4 v = reinterpret_cast<const float4*>(x + (size_t)row * D_)[lane];
    int k = lane * 4;
    float a0 = v.x * Wc[(k + 0) * 2 + 0] + v.y * Wc[(k + 1) * 2 + 0] +
               v.z * Wc[(k + 2) * 2 + 0] + v.w * Wc[(k + 3) * 2 + 0];
    float a1 = v.x * Wc[(k + 0) * 2 + 1] + v.y * Wc[(k + 1) * 2 + 1] +
               v.z * Wc[(k + 2) * 2 + 1] + v.w * Wc[(k + 3) * 2 + 1];
#pragma unroll
    for (int o = 16; o > 0; o >>= 1) {
        a0 += __shfl_xor_sync(0xffffffffu, a0, o);
        a1 += __shfl_xor_sync(0xffffffffu, a1, o);
    }
    if (lane == 0) {
        out[row * 2 + 0] = a0 + bc[0];
        out[row * 2 + 1] = a1 + bc[1];
    }
}

// ---------------- helpers ----------------
static void build_csr(const int* src, const int* dst, int nNodes, int nE,
                      int* cnt, int* rowptr, int* cursor, int* col, int* bsum) {
    int scanBlocks = (nNodes + 1023) / 1024;
    zero_int_kernel<<<(nNodes + 255) / 256, 256>>>(cnt, nNodes);
    hist_kernel<<<(nE + 255) / 256, 256>>>(dst, cnt, nE);
    block_reduce_kernel<<<scanBlocks, 256>>>(cnt, nNodes, bsum);
    scan_small_kernel<<<1, 256>>>(bsum, scanBlocks);
    block_scan_kernel<<<scanBlocks, 256>>>(cnt, nNodes, bsum, rowptr);
    copy_int_kernel<<<(nNodes + 255) / 256, 256>>>(rowptr, cursor, nNodes);
    scatter_kernel<<<(nE + 255) / 256, 256>>>(src, dst, cursor, col, nE);
}

// ---------------- launch ----------------
extern "C" void kernel_launch(void* const* d_in, const int* in_sizes, int n_in,
                              void* d_out, int out_size) {
    const int*   h      = (const int*)d_in[0];
    const int*   gsrc   = (const int*)d_in[1];
    const int*   gdst   = (const int*)d_in[2];
    const int*   fgsrc  = (const int*)d_in[3];
    const int*   fgdst  = (const int*)d_in[4];
    const float* emb    = (const float*)d_in[5];
    const float* W1  = (const float*)d_in[6];
    const float* al1 = (const float*)d_in[7];
    const float* ar1 = (const float*)d_in[8];
    const float* b1  = (const float*)d_in[9];
    const float* W2  = (const float*)d_in[10];
    const float* al2 = (const float*)d_in[11];
    const float* ar2 = (const float*)d_in[12];
    const float* b2  = (const float*)d_in[13];
    const float* W3  = (const float*)d_in[14];
    const float* al3 = (const float*)d_in[15];
    const float* ar3 = (const float*)d_in[16];
    const float* b3  = (const float*)d_in[17];
    const float* Wf  = (const float*)d_in[18];
    const float* bf  = (const float*)d_in[19];
    const float* Wl  = (const float*)d_in[20];
    const float* bl  = (const float*)d_in[21];
    const float* Wl1 = (const float*)d_in[22];
    const float* bl1 = (const float*)d_in[23];
    const float* Wc  = (const float*)d_in[24];
    const float* bc  = (const float*)d_in[25];
    float* out = (float*)d_out;

    float *gx, *gf, *gel, *ger, *pool;
    float *hf, *hx, *hy, *hel, *her;
    int *cnt, *rowptr, *cursor, *col, *bsum;
    int *cntf, *rowptrf, *cursorf, *colf, *bsumf;
    cudaGetSymbolAddress((void**)&gx,  d_gx);
    cudaGetSymbolAddress((void**)&gf,  d_gf);
    cudaGetSymbolAddress((void**)&gel, d_gel);
    cudaGetSymbolAddress((void**)&ger, d_ger);
    cudaGetSymbolAddress((void**)&pool, d_pool);
    cudaGetSymbolAddress((void**)&hf,  d_hf);
    cudaGetSymbolAddress((void**)&hx,  d_hx);
    cudaGetSymbolAddress((void**)&hy,  d_hy);
    cudaGetSymbolAddress((void**)&hel, d_hel);
    cudaGetSymbolAddress((void**)&her, d_her);
    cudaGetSymbolAddress((void**)&cnt,    d_cnt);
    cudaGetSymbolAddress((void**)&rowptr, d_rowptr);
    cudaGetSymbolAddress((void**)&cursor, d_cursor);
    cudaGetSymbolAddress((void**)&col,    d_col);
    cudaGetSymbolAddress((void**)&bsum,   d_bsum);
    cudaGetSymbolAddress((void**)&cntf,    d_cntf);
    cudaGetSymbolAddress((void**)&rowptrf, d_rowptrf);
    cudaGetSymbolAddress((void**)&cursorf, d_cursorf);
    cudaGetSymbolAddress((void**)&colf,    d_colf);
    cudaGetSymbolAddress((void**)&bsumf,   d_bsumf);

    const int ND = N_ * D_;

    // CSR for inner graph (shared by both inner convs) and outer graph
    build_csr(gsrc, gdst, N_, E_, cnt, rowptr, cursor, col, bsum);
    build_csr(fgsrc, fgdst, G_, EF_, cntf, rowptrf, cursorf, colf, bsumf);

    // x = relu(token_emb[h])
    embed_relu_kernel<<<(ND + 255) / 256, 256>>>(h, emb, gx, ND);

    // ---- inner GATConv x2 (fused aggregate + softmax + bias + relu) ----
    for (int conv = 0; conv < 2; conv++) {
        const float* W  = conv == 0 ? W1 : W2;
        const float* al = conv == 0 ? al1 : al2;
        const float* ar = conv == 0 ? ar1 : ar2;
        const float* b  = conv == 0 ? b1 : b2;

        gemm_kernel<128, 8, 8, false, false, true><<<N_ / 128, 256>>>(
            gx, W, nullptr, al, ar, gf, gel, ger, N_, D_);
        gat_aggregate_kernel<<<N_ / 8, 256>>>(rowptr, col, gel, ger, gf, b, gx, N_);
    }

    // linear_forward: f = relu(x @ Wf + bf)
    gemm_kernel<128, 8, 8, true, true, false><<<N_ / 128, 256>>>(
        gx, Wf, bf, nullptr, nullptr, gf, nullptr, nullptr, N_, D_);

    // sort pooling -> pool [2048, 1024]
    sortpool_kernel<<<G_, 256>>>(gf, pool);

    // ---- outer GATConv over fg ----
    gemm_kernel<16, 2, 4, false, false, true><<<G_ / 16, 256>>>(
        pool, W3, nullptr, al3, ar3, hf, hel, her, G_, K_ * D_);
    gat_aggregate_kernel<<<G_ / 8, 256>>>(rowptrf, colf, hel, her, hf, b3, hx, G_);

    // x = relu(x @ Wl + bl); x = relu(x @ Wl1 + bl1)
    gemm_kernel<16, 2, 4, true, true, false><<<G_ / 16, 256>>>(
        hx, Wl, bl, nullptr, nullptr, hy, nullptr, nullptr, G_, D_);
    gemm_kernel<16, 2, 4, true, true, false><<<G_ / 16, 256>>>(
        hy, Wl1, bl1, nullptr, nullptr, hx, nullptr, nullptr, G_, D_);

    // classifier
    classifier_kernel<<<(G_ * 32 + 255) / 256, 256>>>(hx, Wc, bc, out);
}

// round 9
// speedup vs baseline: 2.3316x; 1.5839x over previous
#include <cuda_runtime.h>
#include <cstddef>
#include <cstdint>

// ---------------- problem constants ----------------
constexpr int N_  = 131072;   // inner nodes
constexpr int G_  = 2048;     // graphs / outer nodes
constexpr int E_  = 1048576;  // inner edges
constexpr int EF_ = 32768;    // outer edges
constexpr int D_  = 128;      // feature dim
constexpr int K_  = 8;        // sortpool k

// ---------------- scratch (static device globals; no allocation) ----------------
__device__ float d_gx[(size_t)N_ * D_];
__device__ float d_gf[(size_t)N_ * D_];
__device__ float d_gel[N_];
__device__ float d_ger[N_];
__device__ float d_pool[(size_t)G_ * K_ * D_];
__device__ float d_hf[G_ * D_];
__device__ float d_hx[G_ * D_];
__device__ float d_hy[G_ * D_];
__device__ float d_hel[G_];
__device__ float d_her[G_];

// CSR scratch (inner graph)
__device__ int d_cnt[N_];
__device__ int d_rowptr[N_ + 1];
__device__ int d_cursor[N_];
__device__ int d_col[E_];
__device__ int d_bsum[256];
// CSR scratch (outer graph)
__device__ int d_cntf[G_];
__device__ int d_rowptrf[G_ + 1];
__device__ int d_cursorf[G_];
__device__ int d_colf[EF_];
__device__ int d_bsumf[256];

// ---------------- utility kernels ----------------
__global__ void zero_int_kernel(int* __restrict__ p, int n) {
    int i = blockIdx.x * blockDim.x + threadIdx.x;
    if (i < n) p[i] = 0;
}

__global__ void embed_relu_kernel(const int* __restrict__ h,
                                  const float* __restrict__ emb,
                                  float* __restrict__ x, int total) {
    int i = blockIdx.x * blockDim.x + threadIdx.x;
    if (i >= total) return;
    int node = i >> 7;
    int c = i & 127;
    x[i] = fmaxf(emb[h[node] * D_ + c], 0.f);
}

// ---------------- CSR build ----------------
__global__ void hist_kernel(const int* __restrict__ dst, int* __restrict__ cnt, int nE) {
    int e = blockIdx.x * blockDim.x + threadIdx.x;
    if (e < nE) atomicAdd(&cnt[dst[e]], 1);
}

__global__ void block_reduce_kernel(const int* __restrict__ cnt, int n,
                                    int* __restrict__ bsum) {
    __shared__ int sh[256];
    int base = blockIdx.x * 1024;
    int t = threadIdx.x;
    int s = 0;
#pragma unroll
    for (int i = 0; i < 4; i++) {
        int idx = base + t * 4 + i;
        if (idx < n) s += cnt[idx];
    }
    sh[t] = s;
    __syncthreads();
    for (int o = 128; o > 0; o >>= 1) {
        if (t < o) sh[t] += sh[t + o];
        __syncthreads();
    }
    if (t == 0) bsum[blockIdx.x] = sh[0];
}

__global__ void scan_small_kernel(int* __restrict__ bsum, int nb) {
    __shared__ int sh[256];
    int t = threadIdx.x;
    int orig = t < nb ? bsum[t] : 0;
    sh[t] = orig;
    __syncthreads();
    for (int o = 1; o < 256; o <<= 1) {
        int u = t >= o ? sh[t - o] : 0;
        __syncthreads();
        sh[t] += u;
        __syncthreads();
    }
    if (t < nb) bsum[t] = sh[t] - orig;
}

__global__ void block_scan_kernel(const int* __restrict__ cnt, int n,
                                  const int* __restrict__ bsum,
                                  int* __restrict__ row_ptr) {
    __shared__ int sh[256];
    int base = blockIdx.x * 1024;
    int t = threadIdx.x;
    int v[4];
    int s = 0;
#pragma unroll
    for (int i = 0; i < 4; i++) {
        int idx = base + t * 4 + i;
        v[i] = idx < n ? cnt[idx] : 0;
        s += v[i];
    }
    sh[t] = s;
    __syncthreads();
    for (int o = 1; o < 256; o <<= 1) {
        int u = t >= o ? sh[t - o] : 0;
        __syncthreads();
        sh[t] += u;
        __syncthreads();
    }
    int off = bsum[blockIdx.x] + (t > 0 ? sh[t - 1] : 0);
#pragma unroll
    for (int i = 0; i < 4; i++) {
        int idx = base + t * 4 + i;
        if (idx < n) {
            row_ptr[idx] = off;
            off += v[i];
            if (idx == n - 1) row_ptr[n] = off;
        }
    }
}

__global__ void copy_int_kernel(const int* __restrict__ a, int* __restrict__ b, int n) {
    int i = blockIdx.x * blockDim.x + threadIdx.x;
    if (i < n) b[i] = a[i];
}

__global__ void scatter_kernel(const int* __restrict__ src, const int* __restrict__ dst,
                               int* __restrict__ cursor, int* __restrict__ col, int nE) {
    int e = blockIdx.x * blockDim.x + threadIdx.x;
    if (e >= nE) return;
    int pos = atomicAdd(&cursor[dst[e]], 1);
    col[pos] = src[e];
}

// ---------------- 3xTF32 MMA GEMM: C[M,128] = act(A[M,K] @ B[K,128] (+bias)) ----------------
// Error-compensated: v = hi + lo (hi = tf32(v), lo = tf32(v - hi)).
// acc += a_lo*b_hi + a_hi*b_lo + a_hi*b_hi  (drops only a_lo*b_lo ~ 2^-22).
__device__ __forceinline__ float tf32r(float x) {
    unsigned u;
    asm("cvt.rna.tf32.f32 %0, %1;" : "=r"(u) : "f"(x));
    return __uint_as_float(u);
}

// A smem: swizzled [128][16]: idx(m,k) = m*16 + ((((k>>2)^(m&3))<<2) | (k&3))
__device__ __forceinline__ int As_idx(int m, int k) {
    return m * 16 + ((((k >> 2) ^ (m & 3)) << 2) | (k & 3));
}

#define MMA_TF32(ACC, A0, A1, A2, A3, B0, B1)                                   \
    asm volatile(                                                               \
        "mma.sync.aligned.m16n8k8.row.col.f32.tf32.tf32.f32 "                   \
        "{%0,%1,%2,%3}, {%4,%5,%6,%7}, {%8,%9}, {%0,%1,%2,%3};"                 \
        : "+f"((ACC)[0]), "+f"((ACC)[1]), "+f"((ACC)[2]), "+f"((ACC)[3])        \
        : "r"(A0), "r"(A1), "r"(A2), "r"(A3), "r"(B0), "r"(B1))

template <bool HASBIAS, bool RELU>
__global__ __launch_bounds__(256, 2)
void mma_gemm_kernel(const float* __restrict__ A, const float* __restrict__ B,
                     const float* __restrict__ bias, float* __restrict__ C,
                     int M, int K) {
    constexpr int BM = 128, BN = 128, BK = 16;
    __shared__ float AsH[BM * BK];
    __shared__ float AsL[BM * BK];
    __shared__ float BsH[BK * 132];
    __shared__ float BsL[BK * 132];

    int t = threadIdx.x;
    int lane = t & 31;
    int warp = t >> 5;
    int warp_m = warp >> 1;   // 0..3
    int warp_n = warp & 1;    // 0..1
    int m_block = blockIdx.x * BM;

    float acc[2][8][4];
#pragma unroll
    for (int mi = 0; mi < 2; mi++)
#pragma unroll
        for (int ni = 0; ni < 8; ni++)
#pragma unroll
            for (int c = 0; c < 4; c++) acc[mi][ni][c] = 0.f;

    for (int k0 = 0; k0 < K; k0 += BK) {
        // load A tile 128x16 (512 float4s, 2 per thread), split hi/lo, swizzle
#pragma unroll
        for (int j = 0; j < 2; j++) {
            int idx = t + j * 256;
            int m = idx >> 2;
            int kv = idx & 3;
            float4 v = *reinterpret_cast<const float4*>(
                A + (size_t)(m_block + m) * K + k0 + kv * 4);
            float4 hi, lo;
            hi.x = tf32r(v.x); lo.x = tf32r(v.x - hi.x);
            hi.y = tf32r(v.y); lo.y = tf32r(v.y - hi.y);
            hi.z = tf32r(v.z); lo.z = tf32r(v.z - hi.z);
            hi.w = tf32r(v.w); lo.w = tf32r(v.w - hi.w);
            int kvs = kv ^ (m & 3);
            *reinterpret_cast<float4*>(AsH + m * 16 + kvs * 4) = hi;
            *reinterpret_cast<float4*>(AsL + m * 16 + kvs * 4) = lo;
        }
        // load B tile 16x128 (row-major), padded rows of 132, split hi/lo
#pragma unroll
        for (int j = 0; j < 2; j++) {
            int idx = t + j * 256;
            int k = idx >> 5;
            int nv = idx & 31;
            float4 v = *reinterpret_cast<const float4*>(
                B + (size_t)(k0 + k) * BN + nv * 4);
            float4 hi, lo;
            hi.x = tf32r(v.x); lo.x = tf32r(v.x - hi.x);
            hi.y = tf32r(v.y); lo.y = tf32r(v.y - hi.y);
            hi.z = tf32r(v.z); lo.z = tf32r(v.z - hi.z);
            hi.w = tf32r(v.w); lo.w = tf32r(v.w - hi.w);
            *reinterpret_cast<float4*>(BsH + k * 132 + nv * 4) = hi;
            *reinterpret_cast<float4*>(BsL + k * 132 + nv * 4) = lo;
        }
        __syncthreads();

#pragma unroll
        for (int kk = 0; kk < 2; kk++) {
            int kc = kk * 8 + (lane & 3);
            // A fragments hi+lo
            unsigned aH[2][4], aL[2][4];
#pragma unroll
            for (int mi = 0; mi < 2; mi++) {
                int r0 = warp_m * 32 + mi * 16 + (lane >> 2);
                int r1 = r0 + 8;
                int i00 = As_idx(r0, kc), i10 = As_idx(r1, kc);
                int i01 = As_idx(r0, kc + 4), i11 = As_idx(r1, kc + 4);
                aH[mi][0] = __float_as_uint(AsH[i00]);
                aH[mi][1] = __float_as_uint(AsH[i10]);
                aH[mi][2] = __float_as_uint(AsH[i01]);
                aH[mi][3] = __float_as_uint(AsH[i11]);
                aL[mi][0] = __float_as_uint(AsL[i00]);
                aL[mi][1] = __float_as_uint(AsL[i10]);
                aL[mi][2] = __float_as_uint(AsL[i01]);
                aL[mi][3] = __float_as_uint(AsL[i11]);
            }
#pragma unroll
            for (int ni = 0; ni < 8; ni++) {
                int nn = warp_n * 64 + ni * 8 + (lane >> 2);
                unsigned bH0 = __float_as_uint(BsH[kc * 132 + nn]);
                unsigned bH1 = __float_as_uint(BsH[(kc + 4) * 132 + nn]);
                unsigned bL0 = __float_as_uint(BsL[kc * 132 + nn]);
                unsigned bL1 = __float_as_uint(BsL[(kc + 4) * 132 + nn]);
#pragma unroll
                for (int mi = 0; mi < 2; mi++) {
                    MMA_TF32(acc[mi][ni], aL[mi][0], aL[mi][1], aL[mi][2], aL[mi][3], bH0, bH1);
                    MMA_TF32(acc[mi][ni], aH[mi][0], aH[mi][1], aH[mi][2], aH[mi][3], bL0, bL1);
                    MMA_TF32(acc[mi][ni], aH[mi][0], aH[mi][1], aH[mi][2], aH[mi][3], bH0, bH1);
                }
            }
        }
        __syncthreads();
    }

    // epilogue
#pragma unroll
    for (int mi = 0; mi < 2; mi++) {
        int r = m_block + warp_m * 32 + mi * 16 + (lane >> 2);
#pragma unroll
        for (int ni = 0; ni < 8; ni++) {
            int c = warp_n * 64 + ni * 8 + 2 * (lane & 3);
            float v0 = acc[mi][ni][0], v1 = acc[mi][ni][1];
            float v2 = acc[mi][ni][2], v3 = acc[mi][ni][3];
            if (HASBIAS) {
                float b0 = bias[c], b1 = bias[c + 1];
                v0 += b0; v1 += b1; v2 += b0; v3 += b1;
            }
            if (RELU) {
                v0 = fmaxf(v0, 0.f); v1 = fmaxf(v1, 0.f);
                v2 = fmaxf(v2, 0.f); v3 = fmaxf(v3, 0.f);
            }
            *reinterpret_cast<float2*>(C + (size_t)r * BN + c) = make_float2(v0, v1);
            *reinterpret_cast<float2*>(C + (size_t)(r + 8) * BN + c) = make_float2(v2, v3);
        }
    }
}

// ---------------- attention dots: el[i]=f[i].al, er[i]=f[i].ar (warp per node) ----------------
__global__ void dots_kernel(const float* __restrict__ f,
                            const float* __restrict__ al,
                            const float* __restrict__ ar,
                            float* __restrict__ el, float* __restrict__ er, int n) {
    int node = blockIdx.x * (blockDim.x >> 5) + (threadIdx.x >> 5);
    int lane = threadIdx.x & 31;
    if (node >= n) return;
    float4 v = reinterpret_cast<const float4*>(f)[(size_t)node * 32 + lane];
    float4 a = reinterpret_cast<const float4*>(al)[lane];
    float4 r = reinterpret_cast<const float4*>(ar)[lane];
    float pl = v.x * a.x + v.y * a.y + v.z * a.z + v.w * a.w;
    float pr = v.x * r.x + v.y * r.y + v.z * r.z + v.w * r.w;
#pragma unroll
    for (int o = 16; o > 0; o >>= 1) {
        pl += __shfl_xor_sync(0xffffffffu, pl, o);
        pr += __shfl_xor_sync(0xffffffffu, pr, o);
    }
    if (lane == 0) {
        el[node] = pl;
        er[node] = pr;
    }
}

// ---------------- fused GAT aggregation (warp per dst node, CSR) ----------------
__global__ void gat_aggregate_kernel(const int* __restrict__ row_ptr,
                                     const int* __restrict__ col,
                                     const float* __restrict__ el,
                                     const float* __restrict__ er,
                                     const float* __restrict__ f,
                                     const float* __restrict__ b,
                                     float* __restrict__ outx, int n) {
    int node = blockIdx.x * (blockDim.x >> 5) + (threadIdx.x >> 5);
    int lane = threadIdx.x & 31;
    if (node >= n) return;
    int s0 = row_ptr[node];
    int s1 = row_ptr[node + 1];
    float er_i = er[node];
    const float4* f4 = reinterpret_cast<const float4*>(f);
    float4 acc = {0.f, 0.f, 0.f, 0.f};
    float ssum = 0.f;
    for (int j = s0; j < s1; j++) {
        int s = col[j];
        float e = el[s] + er_i;
        e = e > 0.f ? e : 0.2f * e;
        float a = expf(e);
        ssum += a;
        float4 v = f4[(size_t)s * 32 + lane];
        acc.x += a * v.x;
        acc.y += a * v.y;
        acc.z += a * v.z;
        acc.w += a * v.w;
    }
    float inv = (s1 > s0) ? 1.f / ssum : 0.f;
    int k = lane * 4;
    float4 o;
    o.x = fmaxf(acc.x * inv + b[k + 0], 0.f);
    o.y = fmaxf(acc.y * inv + b[k + 1], 0.f);
    o.z = fmaxf(acc.z * inv + b[k + 2], 0.f);
    o.w = fmaxf(acc.w * inv + b[k + 3], 0.f);
    reinterpret_cast<float4*>(outx)[(size_t)node * 32 + lane] = o;
}

// ---------------- SortPooling ----------------
__global__ void sortpool_kernel(const float* __restrict__ x, float* __restrict__ y) {
    int g = blockIdx.x;
    __shared__ float mx[64];
    __shared__ int sel[8];
    __shared__ float buf[8][128];
    int t = threadIdx.x;
    int w = t >> 5;
    int lane = t & 31;
    const float* xg = x + (size_t)g * 64 * D_;

#pragma unroll
    for (int it = 0; it < 8; it++) {
        int j = w * 8 + it;
        float4 v = reinterpret_cast<const float4*>(xg + (size_t)j * D_)[lane];
        float m = fmaxf(fmaxf(v.x, v.y), fmaxf(v.z, v.w));
#pragma unroll
        for (int o = 16; o > 0; o >>= 1)
            m = fmaxf(m, __shfl_xor_sync(0xffffffffu, m, o));
        if (lane == 0) mx[j] = m;
    }
    __syncthreads();

    if (t < 64) {
        float mj = mx[t];
        int rank = 0;
        for (int i = 0; i < 64; i++) {
            float mi = mx[i];
            rank += (mi > mj) || (mi == mj && i < t);
        }
        if (rank < 8) sel[rank] = t;
    }
    __syncthreads();

    int j = sel[w];
    reinterpret_cast<float4*>(buf[w])[lane] =
        reinterpret_cast<const float4*>(xg + (size_t)j * D_)[lane];
    __syncwarp();
    for (int k2 = 2; k2 <= 128; k2 <<= 1) {
        for (int jj = k2 >> 1; jj > 0; jj >>= 1) {
#pragma unroll
            for (int base = 0; base < 128; base += 32) {
                int i = base + lane;
                int p = i ^ jj;
                if (p > i) {
                    float a = buf[w][i];
                    float bb = buf[w][p];
                    bool up = (i & k2) == 0;
                    if ((a > bb) == up) {
                        buf[w][i] = bb;
                        buf[w][p] = a;
                    }
                }
            }
            __syncwarp();
        }
    }
    reinterpret_cast<float4*>(y + (size_t)g * (K_ * D_) + w * D_)[lane] =
        reinterpret_cast<float4*>(buf[w])[lane];
}

// ---------------- classifier ----------------
__global__ void classifier_kernel(const float* __restrict__ x,
                                  const float* __restrict__ Wc,
                                  const float* __restrict__ bc,
                                  float* __restrict__ out) {
    int row = (blockIdx.x * blockDim.x + threadIdx.x) >> 5;
    int lane = threadIdx.x & 31;
    if (row >= G_) return;
    float4 v = reinterpret_cast<const float4*>(x + (size_t)row * D_)[lane];
    int k = lane * 4;
    float a0 = v.x * Wc[(k + 0) * 2 + 0] + v.y * Wc[(k + 1) * 2 + 0] +
               v.z * Wc[(k + 2) * 2 + 0] + v.w * Wc[(k + 3) * 2 + 0];
    float a1 = v.x * Wc[(k + 0) * 2 + 1] + v.y * Wc[(k + 1) * 2 + 1] +
               v.z * Wc[(k + 2) * 2 + 1] + v.w * Wc[(k + 3) * 2 + 1];
#pragma unroll
    for (int o = 16; o > 0; o >>= 1) {
        a0 += __shfl_xor_sync(0xffffffffu, a0, o);
        a1 += __shfl_xor_sync(0xffffffffu, a1, o);
    }
    if (lane == 0) {
        out[row * 2 + 0] = a0 + bc[0];
        out[row * 2 + 1] = a1 + bc[1];
    }
}

// ---------------- helpers ----------------
static void build_csr(const int* src, const int* dst, int nNodes, int nE,
                      int* cnt, int* rowptr, int* cursor, int* col, int* bsum) {
    int scanBlocks = (nNodes + 1023) / 1024;
    zero_int_kernel<<<(nNodes + 255) / 256, 256>>>(cnt, nNodes);
    hist_kernel<<<(nE + 255) / 256, 256>>>(dst, cnt, nE);
    block_reduce_kernel<<<scanBlocks, 256>>>(cnt, nNodes, bsum);
    scan_small_kernel<<<1, 256>>>(bsum, scanBlocks);
    block_scan_kernel<<<scanBlocks, 256>>>(cnt, nNodes, bsum, rowptr);
    copy_int_kernel<<<(nNodes + 255) / 256, 256>>>(rowptr, cursor, nNodes);
    scatter_kernel<<<(nE + 255) / 256, 256>>>(src, dst, cursor, col, nE);
}

// ---------------- launch ----------------
extern "C" void kernel_launch(void* const* d_in, const int* in_sizes, int n_in,
                              void* d_out, int out_size) {
    const int*   h      = (const int*)d_in[0];
    const int*   gsrc   = (const int*)d_in[1];
    const int*   gdst   = (const int*)d_in[2];
    const int*   fgsrc  = (const int*)d_in[3];
    const int*   fgdst  = (const int*)d_in[4];
    const float* emb    = (const float*)d_in[5];
    const float* W1  = (const float*)d_in[6];
    const float* al1 = (const float*)d_in[7];
    const float* ar1 = (const float*)d_in[8];
    const float* b1  = (const float*)d_in[9];
    const float* W2  = (const float*)d_in[10];
    const float* al2 = (const float*)d_in[11];
    const float* ar2 = (const float*)d_in[12];
    const float* b2  = (const float*)d_in[13];
    const float* W3  = (const float*)d_in[14];
    const float* al3 = (const float*)d_in[15];
    const float* ar3 = (const float*)d_in[16];
    const float* b3  = (const float*)d_in[17];
    const float* Wf  = (const float*)d_in[18];
    const float* bf  = (const float*)d_in[19];
    const float* Wl  = (const float*)d_in[20];
    const float* bl  = (const float*)d_in[21];
    const float* Wl1 = (const float*)d_in[22];
    const float* bl1 = (const float*)d_in[23];
    const float* Wc  = (const float*)d_in[24];
    const float* bc  = (const float*)d_in[25];
    float* out = (float*)d_out;

    float *gx, *gf, *gel, *ger, *pool;
    float *hf, *hx, *hy, *hel, *her;
    int *cnt, *rowptr, *cursor, *col, *bsum;
    int *cntf, *rowptrf, *cursorf, *colf, *bsumf;
    cudaGetSymbolAddress((void**)&gx,  d_gx);
    cudaGetSymbolAddress((void**)&gf,  d_gf);
    cudaGetSymbolAddress((void**)&gel, d_gel);
    cudaGetSymbolAddress((void**)&ger, d_ger);
    cudaGetSymbolAddress((void**)&pool, d_pool);
    cudaGetSymbolAddress((void**)&hf,  d_hf);
    cudaGetSymbolAddress((void**)&hx,  d_hx);
    cudaGetSymbolAddress((void**)&hy,  d_hy);
    cudaGetSymbolAddress((void**)&hel, d_hel);
    cudaGetSymbolAddress((void**)&her, d_her);
    cudaGetSymbolAddress((void**)&cnt,    d_cnt);
    cudaGetSymbolAddress((void**)&rowptr, d_rowptr);
    cudaGetSymbolAddress((void**)&cursor, d_cursor);
    cudaGetSymbolAddress((void**)&col,    d_col);
    cudaGetSymbolAddress((void**)&bsum,   d_bsum);
    cudaGetSymbolAddress((void**)&cntf,    d_cntf);
    cudaGetSymbolAddress((void**)&rowptrf, d_rowptrf);
    cudaGetSymbolAddress((void**)&cursorf, d_cursorf);
    cudaGetSymbolAddress((void**)&colf,    d_colf);
    cudaGetSymbolAddress((void**)&bsumf,   d_bsumf);

    const int ND = N_ * D_;

    build_csr(gsrc, gdst, N_, E_, cnt, rowptr, cursor, col, bsum);
    build_csr(fgsrc, fgdst, G_, EF_, cntf, rowptrf, cursorf, colf, bsumf);

    // x = relu(token_emb[h])
    embed_relu_kernel<<<(ND + 255) / 256, 256>>>(h, emb, gx, ND);

    // ---- inner GATConv x2 ----
    for (int conv = 0; conv < 2; conv++) {
        const float* W  = conv == 0 ? W1 : W2;
        const float* al = conv == 0 ? al1 : al2;
        const float* ar = conv == 0 ? ar1 : ar2;
        const float* b  = conv == 0 ? b1 : b2;

        mma_gemm_kernel<false, false><<<N_ / 128, 256>>>(gx, W, nullptr, gf, N_, 128);
        dots_kernel<<<N_ / 8, 256>>>(gf, al, ar, gel, ger, N_);
        gat_aggregate_kernel<<<N_ / 8, 256>>>(rowptr, col, gel, ger, gf, b, gx, N_);
    }

    // linear_forward: f = relu(x @ Wf + bf)
    mma_gemm_kernel<true, true><<<N_ / 128, 256>>>(gx, Wf, bf, gf, N_, 128);

    // sort pooling -> pool [2048, 1024]
    sortpool_kernel<<<G_, 256>>>(gf, pool);

    // ---- outer GATConv over fg ----
    mma_gemm_kernel<false, false><<<G_ / 128, 256>>>(pool, W3, nullptr, hf, G_, 1024);
    dots_kernel<<<G_ / 8, 256>>>(hf, al3, ar3, hel, her, G_);
    gat_aggregate_kernel<<<G_ / 8, 256>>>(rowptrf, colf, hel, her, hf, b3, hx, G_);

    // x = relu(x @ Wl + bl); x = relu(x @ Wl1 + bl1)
    mma_gemm_kernel<true, true><<<G_ / 128, 256>>>(hx, Wl, bl, hy, G_, 128);
    mma_gemm_kernel<true, true><<<G_ / 128, 256>>>(hy, Wl1, bl1, hx, G_, 128);

    // classifier
    classifier_kernel<<<(G_ * 32 + 255) / 256, 256>>>(hx, Wc, bc, out);
}

// round 10
// speedup vs baseline: 3.0087x; 1.2904x over previous
#include <cuda_runtime.h>
#include <cstddef>
#include <cstdint>

// ---------------- problem constants ----------------
constexpr int N_  = 131072;   // inner nodes
constexpr int G_  = 2048;     // graphs / outer nodes
constexpr int E_  = 1048576;  // inner edges
constexpr int EF_ = 32768;    // outer edges
constexpr int D_  = 128;      // feature dim
constexpr int K_  = 8;        // sortpool k

// ---------------- scratch (static device globals; no allocation) ----------------
__device__ float d_gx[(size_t)N_ * D_];
__device__ float d_gf[(size_t)N_ * D_];
__device__ float d_gel[N_];
__device__ float d_ger[N_];
__device__ float d_pool[(size_t)G_ * K_ * D_];
__device__ float d_hf[G_ * D_];
__device__ float d_hx[G_ * D_];
__device__ float d_hy[G_ * D_];
__device__ float d_hel[G_];
__device__ float d_her[G_];

// CSR scratch (inner graph)
__device__ int d_cnt[N_];
__device__ int d_rowptr[N_ + 1];
__device__ int d_cursor[N_];
__device__ int d_col[E_];
__device__ int d_bsum[256];
// CSR scratch (outer graph)
__device__ int d_cntf[G_];
__device__ int d_rowptrf[G_ + 1];
__device__ int d_cursorf[G_];
__device__ int d_colf[EF_];
__device__ int d_bsumf[256];

// ---------------- utility kernels ----------------
__global__ void zero_int_kernel(int* __restrict__ p, int n) {
    int i = blockIdx.x * blockDim.x + threadIdx.x;
    if (i < n) p[i] = 0;
}

__global__ void zero_float_kernel(float* __restrict__ p, int n) {
    int i = blockIdx.x * blockDim.x + threadIdx.x;
    if (i < n) p[i] = 0.f;
}

// ---------------- CSR build ----------------
__global__ void hist_kernel(const int* __restrict__ dst, int* __restrict__ cnt, int nE) {
    int e = blockIdx.x * blockDim.x + threadIdx.x;
    if (e < nE) atomicAdd(&cnt[dst[e]], 1);
}

__global__ void block_reduce_kernel(const int* __restrict__ cnt, int n,
                                    int* __restrict__ bsum) {
    __shared__ int sh[256];
    int base = blockIdx.x * 1024;
    int t = threadIdx.x;
    int s = 0;
#pragma unroll
    for (int i = 0; i < 4; i++) {
        int idx = base + t * 4 + i;
        if (idx < n) s += cnt[idx];
    }
    sh[t] = s;
    __syncthreads();
    for (int o = 128; o > 0; o >>= 1) {
        if (t < o) sh[t] += sh[t + o];
        __syncthreads();
    }
    if (t == 0) bsum[blockIdx.x] = sh[0];
}

__global__ void scan_small_kernel(int* __restrict__ bsum, int nb) {
    __shared__ int sh[256];
    int t = threadIdx.x;
    int orig = t < nb ? bsum[t] : 0;
    sh[t] = orig;
    __syncthreads();
    for (int o = 1; o < 256; o <<= 1) {
        int u = t >= o ? sh[t - o] : 0;
        __syncthreads();
        sh[t] += u;
        __syncthreads();
    }
    if (t < nb) bsum[t] = sh[t] - orig;
}

// per-block exclusive scan with block offset; emits row_ptr AND cursor copy
__global__ void block_scan_kernel(const int* __restrict__ cnt, int n,
                                  const int* __restrict__ bsum,
                                  int* __restrict__ row_ptr,
                                  int* __restrict__ cursor) {
    __shared__ int sh[256];
    int base = blockIdx.x * 1024;
    int t = threadIdx.x;
    int v[4];
    int s = 0;
#pragma unroll
    for (int i = 0; i < 4; i++) {
        int idx = base + t * 4 + i;
        v[i] = idx < n ? cnt[idx] : 0;
        s += v[i];
    }
    sh[t] = s;
    __syncthreads();
    for (int o = 1; o < 256; o <<= 1) {
        int u = t >= o ? sh[t - o] : 0;
        __syncthreads();
        sh[t] += u;
        __syncthreads();
    }
    int off = bsum[blockIdx.x] + (t > 0 ? sh[t - 1] : 0);
#pragma unroll
    for (int i = 0; i < 4; i++) {
        int idx = base + t * 4 + i;
        if (idx < n) {
            row_ptr[idx] = off;
            cursor[idx] = off;
            off += v[i];
            if (idx == n - 1) row_ptr[n] = off;
        }
    }
}

__global__ void scatter_kernel(const int* __restrict__ src, const int* __restrict__ dst,
                               int* __restrict__ cursor, int* __restrict__ col, int nE) {
    int e = blockIdx.x * blockDim.x + threadIdx.x;
    if (e >= nE) return;
    int pos = atomicAdd(&cursor[dst[e]], 1);
    col[pos] = src[e];
}

// ---------------- 3xTF32 MMA GEMM ----------------
// C[M,128] = act(A[M,K] @ B[K,128] (+bias))
// GATHER: A row m is relu(emb[hidx[m]]) (K must be 128)
// DOTS:   also emit el[m]=C_row.al, er[m]=C_row.ar (pre-activation C)
// SPLITK: gridDim.y k-chunks of 128; epilogue atomicAdd into C (no bias/relu/dots)
__device__ __forceinline__ float tf32r(float x) {
    unsigned u;
    asm("cvt.rna.tf32.f32 %0, %1;" : "=r"(u) : "f"(x));
    return __uint_as_float(u);
}

__device__ __forceinline__ int As_idx(int m, int k) {
    return m * 16 + ((((k >> 2) ^ (m & 3)) << 2) | (k & 3));
}

#define MMA_TF32(ACC, A0, A1, A2, A3, B0, B1)                                   \
    asm volatile(                                                               \
        "mma.sync.aligned.m16n8k8.row.col.f32.tf32.tf32.f32 "                   \
        "{%0,%1,%2,%3}, {%4,%5,%6,%7}, {%8,%9}, {%0,%1,%2,%3};"                 \
        : "+f"((ACC)[0]), "+f"((ACC)[1]), "+f"((ACC)[2]), "+f"((ACC)[3])        \
        : "r"(A0), "r"(A1), "r"(A2), "r"(A3), "r"(B0), "r"(B1))

template <bool HASBIAS, bool RELU, bool DOTS, bool GATHER, bool SPLITK>
__global__ __launch_bounds__(256, 2)
void mma_gemm_kernel(const float* __restrict__ A, const float* __restrict__ B,
                     const float* __restrict__ bias,
                     const float* __restrict__ al, const float* __restrict__ ar,
                     const int* __restrict__ hidx,
                     float* __restrict__ C,
                     float* __restrict__ el, float* __restrict__ er,
                     int M, int K) {
    constexpr int BM = 128, BN = 128, BK = 16;
    __shared__ float AsH[BM * BK];
    __shared__ float AsL[BM * BK];
    __shared__ float BsH[BK * 132];
    __shared__ float BsL[BK * 132];
    __shared__ float sPL[128], sPR[128];

    int t = threadIdx.x;
    int lane = t & 31;
    int warp = t >> 5;
    int warp_m = warp >> 1;   // 0..3
    int warp_n = warp & 1;    // 0..1
    int m_block = blockIdx.x * BM;

    float acc[2][8][4];
#pragma unroll
    for (int mi = 0; mi < 2; mi++)
#pragma unroll
        for (int ni = 0; ni < 8; ni++)
#pragma unroll
            for (int c = 0; c < 4; c++) acc[mi][ni][c] = 0.f;

    int kstart = SPLITK ? blockIdx.y * 128 : 0;
    int kend   = SPLITK ? kstart + 128 : K;

    for (int k0 = kstart; k0 < kend; k0 += BK) {
        // load A tile 128x16 (512 float4s, 2 per thread), split hi/lo, swizzle
#pragma unroll
        for (int j = 0; j < 2; j++) {
            int idx = t + j * 256;
            int m = idx >> 2;
            int kv = idx & 3;
            const float* arow;
            if constexpr (GATHER)
                arow = A + (size_t)hidx[m_block + m] * 128;
            else
                arow = A + (size_t)(m_block + m) * K;
            float4 v = *reinterpret_cast<const float4*>(arow + k0 + kv * 4);
            if constexpr (GATHER) {
                v.x = fmaxf(v.x, 0.f); v.y = fmaxf(v.y, 0.f);
                v.z = fmaxf(v.z, 0.f); v.w = fmaxf(v.w, 0.f);
            }
            float4 hi, lo;
            hi.x = tf32r(v.x); lo.x = tf32r(v.x - hi.x);
            hi.y = tf32r(v.y); lo.y = tf32r(v.y - hi.y);
            hi.z = tf32r(v.z); lo.z = tf32r(v.z - hi.z);
            hi.w = tf32r(v.w); lo.w = tf32r(v.w - hi.w);
            int kvs = kv ^ (m & 3);
            *reinterpret_cast<float4*>(AsH + m * 16 + kvs * 4) = hi;
            *reinterpret_cast<float4*>(AsL + m * 16 + kvs * 4) = lo;
        }
        // load B tile 16x128 (row-major), padded rows of 132, split hi/lo
#pragma unroll
        for (int j = 0; j < 2; j++) {
            int idx = t + j * 256;
            int k = idx >> 5;
            int nv = idx & 31;
            float4 v = *reinterpret_cast<const float4*>(
                B + (size_t)(k0 + k) * BN + nv * 4);
            float4 hi, lo;
            hi.x = tf32r(v.x); lo.x = tf32r(v.x - hi.x);
            hi.y = tf32r(v.y); lo.y = tf32r(v.y - hi.y);
            hi.z = tf32r(v.z); lo.z = tf32r(v.z - hi.z);
            hi.w = tf32r(v.w); lo.w = tf32r(v.w - hi.w);
            *reinterpret_cast<float4*>(BsH + k * 132 + nv * 4) = hi;
            *reinterpret_cast<float4*>(BsL + k * 132 + nv * 4) = lo;
        }
        __syncthreads();

#pragma unroll
        for (int kk = 0; kk < 2; kk++) {
            int kc = kk * 8 + (lane & 3);
            unsigned aH[2][4], aL[2][4];
#pragma unroll
            for (int mi = 0; mi < 2; mi++) {
                int r0 = warp_m * 32 + mi * 16 + (lane >> 2);
                int r1 = r0 + 8;
                int i00 = As_idx(r0, kc), i10 = As_idx(r1, kc);
                int i01 = As_idx(r0, kc + 4), i11 = As_idx(r1, kc + 4);
                aH[mi][0] = __float_as_uint(AsH[i00]);
                aH[mi][1] = __float_as_uint(AsH[i10]);
                aH[mi][2] = __float_as_uint(AsH[i01]);
                aH[mi][3] = __float_as_uint(AsH[i11]);
                aL[mi][0] = __float_as_uint(AsL[i00]);
                aL[mi][1] = __float_as_uint(AsL[i10]);
                aL[mi][2] = __float_as_uint(AsL[i01]);
                aL[mi][3] = __float_as_uint(AsL[i11]);
            }
#pragma unroll
            for (int ni = 0; ni < 8; ni++) {
                int nn = warp_n * 64 + ni * 8 + (lane >> 2);
                unsigned bH0 = __float_as_uint(BsH[kc * 132 + nn]);
                unsigned bH1 = __float_as_uint(BsH[(kc + 4) * 132 + nn]);
                unsigned bL0 = __float_as_uint(BsL[kc * 132 + nn]);
                unsigned bL1 = __float_as_uint(BsL[(kc + 4) * 132 + nn]);
#pragma unroll
                for (int mi = 0; mi < 2; mi++) {
                    MMA_TF32(acc[mi][ni], aL[mi][0], aL[mi][1], aL[mi][2], aL[mi][3], bH0, bH1);
                    MMA_TF32(acc[mi][ni], aH[mi][0], aH[mi][1], aH[mi][2], aH[mi][3], bL0, bL1);
                    MMA_TF32(acc[mi][ni], aH[mi][0], aH[mi][1], aH[mi][2], aH[mi][3], bH0, bH1);
                }
            }
        }
        __syncthreads();
    }

    // ---- epilogue: store C ----
#pragma unroll
    for (int mi = 0; mi < 2; mi++) {
        int r = m_block + warp_m * 32 + mi * 16 + (lane >> 2);
#pragma unroll
        for (int ni = 0; ni < 8; ni++) {
            int c = warp_n * 64 + ni * 8 + 2 * (lane & 3);
            float v0 = acc[mi][ni][0], v1 = acc[mi][ni][1];
            float v2 = acc[mi][ni][2], v3 = acc[mi][ni][3];
            if constexpr (SPLITK) {
                atomicAdd(C + (size_t)r * BN + c, v0);
                atomicAdd(C + (size_t)r * BN + c + 1, v1);
                atomicAdd(C + (size_t)(r + 8) * BN + c, v2);
                atomicAdd(C + (size_t)(r + 8) * BN + c + 1, v3);
            } else {
                if (HASBIAS) {
                    float b0 = bias[c], b1 = bias[c + 1];
                    v0 += b0; v1 += b1; v2 += b0; v3 += b1;
                }
                if (RELU) {
                    v0 = fmaxf(v0, 0.f); v1 = fmaxf(v1, 0.f);
                    v2 = fmaxf(v2, 0.f); v3 = fmaxf(v3, 0.f);
                }
                *reinterpret_cast<float2*>(C + (size_t)r * BN + c) = make_float2(v0, v1);
                *reinterpret_cast<float2*>(C + (size_t)(r + 8) * BN + c) = make_float2(v2, v3);
            }
        }
    }

    // ---- fused attention dots (no atomics: quad shfl + cross-warp smem) ----
    if constexpr (DOTS) {
        float qpl[2][2], qpr[2][2];
#pragma unroll
        for (int mi = 0; mi < 2; mi++) {
            float pl0 = 0.f, pr0 = 0.f, pl1 = 0.f, pr1 = 0.f;
#pragma unroll
            for (int ni = 0; ni < 8; ni++) {
                int c = warp_n * 64 + ni * 8 + 2 * (lane & 3);
                float a0 = al[c], a1 = al[c + 1];
                float g0 = ar[c], g1 = ar[c + 1];
                pl0 += acc[mi][ni][0] * a0 + acc[mi][ni][1] * a1;
                pr0 += acc[mi][ni][0] * g0 + acc[mi][ni][1] * g1;
                pl1 += acc[mi][ni][2] * a0 + acc[mi][ni][3] * a1;
                pr1 += acc[mi][ni][2] * g0 + acc[mi][ni][3] * g1;
            }
#pragma unroll
            for (int o = 1; o <= 2; o <<= 1) {
                pl0 += __shfl_xor_sync(0xffffffffu, pl0, o);
                pr0 += __shfl_xor_sync(0xffffffffu, pr0, o);
                pl1 += __shfl_xor_sync(0xffffffffu, pl1, o);
                pr1 += __shfl_xor_sync(0xffffffffu, pr1, o);
            }
            qpl[mi][0] = pl0; qpl[mi][1] = pl1;
            qpr[mi][0] = pr0; qpr[mi][1] = pr1;
        }
        if ((lane & 3) == 0 && warp_n == 0) {
#pragma unroll
            for (int mi = 0; mi < 2; mi++) {
                int lr = warp_m * 32 + mi * 16 + (lane >> 2);
                sPL[lr] = qpl[mi][0]; sPR[lr] = qpr[mi][0];
                sPL[lr + 8] = qpl[mi][1]; sPR[lr + 8] = qpr[mi][1];
            }
        }
        __syncthreads();
        if ((lane & 3) == 0 && warp_n == 1) {
#pragma unroll
            for (int mi = 0; mi < 2; mi++) {
                int lr = warp_m * 32 + mi * 16 + (lane >> 2);
                el[m_block + lr] = sPL[lr] + qpl[mi][0];
                er[m_block + lr] = sPR[lr] + qpr[mi][0];
                el[m_block + lr + 8] = sPL[lr + 8] + qpl[mi][1];
                er[m_block + lr + 8] = sPR[lr + 8] + qpr[mi][1];
            }
        }
    }
}

// ---------------- small dots (outer graph only) ----------------
__global__ void dots_kernel(const float* __restrict__ f,
                            const float* __restrict__ al,
                            const float* __restrict__ ar,
                            float* __restrict__ el, float* __restrict__ er, int n) {
    int node = blockIdx.x * (blockDim.x >> 5) + (threadIdx.x >> 5);
    int lane = threadIdx.x & 31;
    if (node >= n) return;
    float4 v = reinterpret_cast<const float4*>(f)[(size_t)node * 32 + lane];
    float4 a = reinterpret_cast<const float4*>(al)[lane];
    float4 r = reinterpret_cast<const float4*>(ar)[lane];
    float pl = v.x * a.x + v.y * a.y + v.z * a.z + v.w * a.w;
    float pr = v.x * r.x + v.y * r.y + v.z * r.z + v.w * r.w;
#pragma unroll
    for (int o = 16; o > 0; o >>= 1) {
        pl += __shfl_xor_sync(0xffffffffu, pl, o);
        pr += __shfl_xor_sync(0xffffffffu, pr, o);
    }
    if (lane == 0) {
        el[node] = pl;
        er[node] = pr;
    }
}

// ---------------- fused GAT aggregation (warp per dst node, CSR) ----------------
__global__ void gat_aggregate_kernel(const int* __restrict__ row_ptr,
                                     const int* __restrict__ col,
                                     const float* __restrict__ el,
                                     const float* __restrict__ er,
                                     const float* __restrict__ f,
                                     const float* __restrict__ b,
                                     float* __restrict__ outx, int n) {
    int node = blockIdx.x * (blockDim.x >> 5) + (threadIdx.x >> 5);
    int lane = threadIdx.x & 31;
    if (node >= n) return;
    int s0 = row_ptr[node];
    int s1 = row_ptr[node + 1];
    float er_i = er[node];
    const float4* f4 = reinterpret_cast<const float4*>(f);
    float4 acc = {0.f, 0.f, 0.f, 0.f};
    float ssum = 0.f;
    for (int j = s0; j < s1; j++) {
        int s = col[j];
        float e = el[s] + er_i;
        e = e > 0.f ? e : 0.2f * e;
        float a = expf(e);
        ssum += a;
        float4 v = f4[(size_t)s * 32 + lane];
        acc.x += a * v.x;
        acc.y += a * v.y;
        acc.z += a * v.z;
        acc.w += a * v.w;
    }
    float inv = (s1 > s0) ? 1.f / ssum : 0.f;
    int k = lane * 4;
    float4 o;
    o.x = fmaxf(acc.x * inv + b[k + 0], 0.f);
    o.y = fmaxf(acc.y * inv + b[k + 1], 0.f);
    o.z = fmaxf(acc.z * inv + b[k + 2], 0.f);
    o.w = fmaxf(acc.w * inv + b[k + 3], 0.f);
    reinterpret_cast<float4*>(outx)[(size_t)node * 32 + lane] = o;
}

// ---------------- SortPooling ----------------
__global__ void sortpool_kernel(const float* __restrict__ x, float* __restrict__ y) {
    int g = blockIdx.x;
    __shared__ float mx[64];
    __shared__ int sel[8];
    __shared__ float buf[8][128];
    int t = threadIdx.x;
    int w = t >> 5;
    int lane = t & 31;
    const float* xg = x + (size_t)g * 64 * D_;

#pragma unroll
    for (int it = 0; it < 8; it++) {
        int j = w * 8 + it;
        float4 v = reinterpret_cast<const float4*>(xg + (size_t)j * D_)[lane];
        float m = fmaxf(fmaxf(v.x, v.y), fmaxf(v.z, v.w));
#pragma unroll
        for (int o = 16; o > 0; o >>= 1)
            m = fmaxf(m, __shfl_xor_sync(0xffffffffu, m, o));
        if (lane == 0) mx[j] = m;
    }
    __syncthreads();

    if (t < 64) {
        float mj = mx[t];
        int rank = 0;
        for (int i = 0; i < 64; i++) {
            float mi = mx[i];
            rank += (mi > mj) || (mi == mj && i < t);
        }
        if (rank < 8) sel[rank] = t;
    }
    __syncthreads();

    int j = sel[w];
    reinterpret_cast<float4*>(buf[w])[lane] =
        reinterpret_cast<const float4*>(xg + (size_t)j * D_)[lane];
    __syncwarp();
    for (int k2 = 2; k2 <= 128; k2 <<= 1) {
        for (int jj = k2 >> 1; jj > 0; jj >>= 1) {
#pragma unroll
            for (int base = 0; base < 128; base += 32) {
                int i = base + lane;
                int p = i ^ jj;
                if (p > i) {
                    float a = buf[w][i];
                    float bb = buf[w][p];
                    bool up = (i & k2) == 0;
                    if ((a > bb) == up) {
                        buf[w][i] = bb;
                        buf[w][p] = a;
                    }
                }
            }
            __syncwarp();
        }
    }
    reinterpret_cast<float4*>(y + (size_t)g * (K_ * D_) + w * D_)[lane] =
        reinterpret_cast<float4*>(buf[w])[lane];
}

// ---------------- classifier ----------------
__global__ void classifier_kernel(const float* __restrict__ x,
                                  const float* __restrict__ Wc,
                                  const float* __restrict__ bc,
                                  float* __restrict__ out) {
    int row = (blockIdx.x * blockDim.x + threadIdx.x) >> 5;
    int lane = threadIdx.x & 31;
    if (row >= G_) return;
    float4 v = reinterpret_cast<const float4*>(x + (size_t)row * D_)[lane];
    int k = lane * 4;
    float a0 = v.x * Wc[(k + 0) * 2 + 0] + v.y * Wc[(k + 1) * 2 + 0] +
               v.z * Wc[(k + 2) * 2 + 0] + v.w * Wc[(k + 3) * 2 + 0];
    float a1 = v.x * Wc[(k + 0) * 2 + 1] + v.y * Wc[(k + 1) * 2 + 1] +
               v.z * Wc[(k + 2) * 2 + 1] + v.w * Wc[(k + 3) * 2 + 1];
#pragma unroll
    for (int o = 16; o > 0; o >>= 1) {
        a0 += __shfl_xor_sync(0xffffffffu, a0, o);
        a1 += __shfl_xor_sync(0xffffffffu, a1, o);
    }
    if (lane == 0) {
        out[row * 2 + 0] = a0 + bc[0];
        out[row * 2 + 1] = a1 + bc[1];
    }
}

// ---------------- helpers ----------------
static void build_csr(const int* src, const int* dst, int nNodes, int nE,
                      int* cnt, int* rowptr, int* cursor, int* col, int* bsum) {
    int scanBlocks = (nNodes + 1023) / 1024;
    zero_int_kernel<<<(nNodes + 255) / 256, 256>>>(cnt, nNodes);
    hist_kernel<<<(nE + 255) / 256, 256>>>(dst, cnt, nE);
    block_reduce_kernel<<<scanBlocks, 256>>>(cnt, nNodes, bsum);
    scan_small_kernel<<<1, 256>>>(bsum, scanBlocks);
    block_scan_kernel<<<scanBlocks, 256>>>(cnt, nNodes, bsum, rowptr, cursor);
    scatter_kernel<<<(nE + 255) / 256, 256>>>(src, dst, cursor, col, nE);
}

// ---------------- launch ----------------
extern "C" void kernel_launch(void* const* d_in, const int* in_sizes, int n_in,
                              void* d_out, int out_size) {
    const int*   h      = (const int*)d_in[0];
    const int*   gsrc   = (const int*)d_in[1];
    const int*   gdst   = (const int*)d_in[2];
    const int*   fgsrc  = (const int*)d_in[3];
    const int*   fgdst  = (const int*)d_in[4];
    const float* emb    = (const float*)d_in[5];
    const float* W1  = (const float*)d_in[6];
    const float* al1 = (const float*)d_in[7];
    const float* ar1 = (const float*)d_in[8];
    const float* b1  = (const float*)d_in[9];
    const float* W2  = (const float*)d_in[10];
    const float* al2 = (const float*)d_in[11];
    const float* ar2 = (const float*)d_in[12];
    const float* b2  = (const float*)d_in[13];
    const float* W3  = (const float*)d_in[14];
    const float* al3 = (const float*)d_in[15];
    const float* ar3 = (const float*)d_in[16];
    const float* b3  = (const float*)d_in[17];
    const float* Wf  = (const float*)d_in[18];
    const float* bf  = (const float*)d_in[19];
    const float* Wl  = (const float*)d_in[20];
    const float* bl  = (const float*)d_in[21];
    const float* Wl1 = (const float*)d_in[22];
    const float* bl1 = (const float*)d_in[23];
    const float* Wc  = (const float*)d_in[24];
    const float* bc  = (const float*)d_in[25];
    float* out = (float*)d_out;

    float *gx, *gf, *gel, *ger, *pool;
    float *hf, *hx, *hy, *hel, *her;
    int *cnt, *rowptr, *cursor, *col, *bsum;
    int *cntf, *rowptrf, *cursorf, *colf, *bsumf;
    cudaGetSymbolAddress((void**)&gx,  d_gx);
    cudaGetSymbolAddress((void**)&gf,  d_gf);
    cudaGetSymbolAddress((void**)&gel, d_gel);
    cudaGetSymbolAddress((void**)&ger, d_ger);
    cudaGetSymbolAddress((void**)&pool, d_pool);
    cudaGetSymbolAddress((void**)&hf,  d_hf);
    cudaGetSymbolAddress((void**)&hx,  d_hx);
    cudaGetSymbolAddress((void**)&hy,  d_hy);
    cudaGetSymbolAddress((void**)&hel, d_hel);
    cudaGetSymbolAddress((void**)&her, d_her);
    cudaGetSymbolAddress((void**)&cnt,    d_cnt);
    cudaGetSymbolAddress((void**)&rowptr, d_rowptr);
    cudaGetSymbolAddress((void**)&cursor, d_cursor);
    cudaGetSymbolAddress((void**)&col,    d_col);
    cudaGetSymbolAddress((void**)&bsum,   d_bsum);
    cudaGetSymbolAddress((void**)&cntf,    d_cntf);
    cudaGetSymbolAddress((void**)&rowptrf, d_rowptrf);
    cudaGetSymbolAddress((void**)&cursorf, d_cursorf);
    cudaGetSymbolAddress((void**)&colf,    d_colf);
    cudaGetSymbolAddress((void**)&bsumf,   d_bsumf);

    build_csr(gsrc, gdst, N_, E_, cnt, rowptr, cursor, col, bsum);
    build_csr(fgsrc, fgdst, G_, EF_, cntf, rowptrf, cursorf, colf, bsumf);

    // ---- inner GATConv 1 (embed fused into A-loader, dots fused in epilogue) ----
    mma_gemm_kernel<false, false, true, true, false><<<N_ / 128, 256>>>(
        emb, W1, nullptr, al1, ar1, h, gf, gel, ger, N_, 128);
    gat_aggregate_kernel<<<N_ / 8, 256>>>(rowptr, col, gel, ger, gf, b1, gx, N_);

    // ---- inner GATConv 2 ----
    mma_gemm_kernel<false, false, true, false, false><<<N_ / 128, 256>>>(
        gx, W2, nullptr, al2, ar2, nullptr, gf, gel, ger, N_, 128);
    gat_aggregate_kernel<<<N_ / 8, 256>>>(rowptr, col, gel, ger, gf, b2, gx, N_);

    // linear_forward: f = relu(x @ Wf + bf)
    mma_gemm_kernel<true, true, false, false, false><<<N_ / 128, 256>>>(
        gx, Wf, bf, nullptr, nullptr, nullptr, gf, nullptr, nullptr, N_, 128);

    // sort pooling -> pool [2048, 1024]
    sortpool_kernel<<<G_, 256>>>(gf, pool);

    // ---- outer GATConv over fg (split-K GEMM: 16 x 8 blocks) ----
    zero_float_kernel<<<(G_ * D_ + 255) / 256, 256>>>(hf, G_ * D_);
    {
        dim3 grid(G_ / 128, 8);
        mma_gemm_kernel<false, false, false, false, true><<<grid, 256>>>(
            pool, W3, nullptr, nullptr, nullptr, nullptr, hf, nullptr, nullptr, G_, 1024);
    }
    dots_kernel<<<G_ / 8, 256>>>(hf, al3, ar3, hel, her, G_);
    gat_aggregate_kernel<<<G_ / 8, 256>>>(rowptrf, colf, hel, her, hf, b3, hx, G_);

    // x = relu(x @ Wl + bl); x = relu(x @ Wl1 + bl1)
    mma_gemm_kernel<true, true, false, false, false><<<G_ / 128, 256>>>(
        hx, Wl, bl, nullptr, nullptr, nullptr, hy, nullptr, nullptr, G_, 128);
    mma_gemm_kernel<true, true, false, false, false><<<G_ / 128, 256>>>(
        hy, Wl1, bl1, nullptr, nullptr, nullptr, hx, nullptr, nullptr, G_, 128);

    // classifier
    classifier_kernel<<<(G_ * 32 + 255) / 256, 256>>>(hx, Wc, bc, out);
}

// round 11
// speedup vs baseline: 3.1355x; 1.0421x over previous
#include <cuda_runtime.h>
#include <cstddef>
#include <cstdint>

// ---------------- problem constants ----------------
constexpr int N_  = 131072;   // inner nodes
constexpr int G_  = 2048;     // graphs / outer nodes
constexpr int E_  = 1048576;  // inner edges
constexpr int EF_ = 32768;    // outer edges
constexpr int D_  = 128;      // feature dim
constexpr int K_  = 8;        // sortpool k
constexpr int NODES_ALL = N_ + G_;        // combined CSR node space
constexpr int EDGES_ALL = E_ + EF_;       // combined CSR edge space

// ---------------- scratch (static device globals; no allocation) ----------------
__device__ float d_gx[(size_t)N_ * D_];
__device__ float d_gf[(size_t)N_ * D_];
__device__ float d_gel[N_];
__device__ float d_ger[N_];
__device__ float d_pool[(size_t)G_ * K_ * D_];
__device__ float d_hf[G_ * D_];
__device__ float d_hx[G_ * D_];
__device__ float d_hy[G_ * D_];
__device__ float d_hel[G_];
__device__ float d_her[G_];

// combined CSR scratch (inner graph nodes 0..N_-1, outer at N_..N_+G_-1)
__device__ int d_cnt[NODES_ALL];
__device__ int d_rowptr[NODES_ALL + 1];
__device__ int d_cursor[NODES_ALL];
__device__ int d_col[EDGES_ALL];
__device__ int d_bsum[256];

// ---------------- utility kernels ----------------
__global__ void zero_int_kernel(int* __restrict__ p, int n) {
    int i = blockIdx.x * blockDim.x + threadIdx.x;
    if (i < n) p[i] = 0;
}

__global__ void zero_float_kernel(float* __restrict__ p, int n) {
    int i = blockIdx.x * blockDim.x + threadIdx.x;
    if (i < n) p[i] = 0.f;
}

// ---------------- combined CSR build ----------------
__global__ void hist2_kernel(const int* __restrict__ gdst,
                             const int* __restrict__ fgdst,
                             int* __restrict__ cnt) {
    int e = blockIdx.x * blockDim.x + threadIdx.x;
    if (e < E_) atomicAdd(&cnt[gdst[e]], 1);
    else if (e < EDGES_ALL) atomicAdd(&cnt[N_ + fgdst[e - E_]], 1);
}

__global__ void block_reduce_kernel(const int* __restrict__ cnt, int n,
                                    int* __restrict__ bsum) {
    __shared__ int sh[256];
    int base = blockIdx.x * 1024;
    int t = threadIdx.x;
    int s = 0;
#pragma unroll
    for (int i = 0; i < 4; i++) {
        int idx = base + t * 4 + i;
        if (idx < n) s += cnt[idx];
    }
    sh[t] = s;
    __syncthreads();
    for (int o = 128; o > 0; o >>= 1) {
        if (t < o) sh[t] += sh[t + o];
        __syncthreads();
    }
    if (t == 0) bsum[blockIdx.x] = sh[0];
}

__global__ void scan_small_kernel(int* __restrict__ bsum, int nb) {
    __shared__ int sh[256];
    int t = threadIdx.x;
    int orig = t < nb ? bsum[t] : 0;
    sh[t] = orig;
    __syncthreads();
    for (int o = 1; o < 256; o <<= 1) {
        int u = t >= o ? sh[t - o] : 0;
        __syncthreads();
        sh[t] += u;
        __syncthreads();
    }
    if (t < nb) bsum[t] = sh[t] - orig;
}

__global__ void block_scan_kernel(const int* __restrict__ cnt, int n,
                                  const int* __restrict__ bsum,
                                  int* __restrict__ row_ptr,
                                  int* __restrict__ cursor) {
    __shared__ int sh[256];
    int base = blockIdx.x * 1024;
    int t = threadIdx.x;
    int v[4];
    int s = 0;
#pragma unroll
    for (int i = 0; i < 4; i++) {
        int idx = base + t * 4 + i;
        v[i] = idx < n ? cnt[idx] : 0;
        s += v[i];
    }
    sh[t] = s;
    __syncthreads();
    for (int o = 1; o < 256; o <<= 1) {
        int u = t >= o ? sh[t - o] : 0;
        __syncthreads();
        sh[t] += u;
        __syncthreads();
    }
    int off = bsum[blockIdx.x] + (t > 0 ? sh[t - 1] : 0);
#pragma unroll
    for (int i = 0; i < 4; i++) {
        int idx = base + t * 4 + i;
        if (idx < n) {
            row_ptr[idx] = off;
            cursor[idx] = off;
            off += v[i];
            if (idx == n - 1) row_ptr[n] = off;
        }
    }
}

__global__ void scatter2_kernel(const int* __restrict__ gsrc, const int* __restrict__ gdst,
                                const int* __restrict__ fgsrc, const int* __restrict__ fgdst,
                                int* __restrict__ cursor, int* __restrict__ col) {
    int e = blockIdx.x * blockDim.x + threadIdx.x;
    if (e < E_) {
        int pos = atomicAdd(&cursor[gdst[e]], 1);
        col[pos] = gsrc[e];
    } else if (e < EDGES_ALL) {
        int ef = e - E_;
        int pos = atomicAdd(&cursor[N_ + fgdst[ef]], 1);
        col[pos] = fgsrc[ef];
    }
}

// ---------------- 3xTF32 MMA GEMM (software-pipelined) ----------------
// C[M,128] = act(A[M,K] @ B[K,128] (+bias))
// GATHER: A row m is relu(emb[hidx[m]]) (K must be 128)
// DOTS:   also emit el[m]=C_row.al, er[m]=C_row.ar (pre-activation C)
// SPLITK: gridDim.y k-chunks of 128; epilogue atomicAdd into C
__device__ __forceinline__ float tf32r(float x) {
    unsigned u;
    asm("cvt.rna.tf32.f32 %0, %1;" : "=r"(u) : "f"(x));
    return __uint_as_float(u);
}

__device__ __forceinline__ int As_idx(int m, int k) {
    return m * 16 + ((((k >> 2) ^ (m & 3)) << 2) | (k & 3));
}

#define MMA_TF32(ACC, A0, A1, A2, A3, B0, B1)                                   \
    asm volatile(                                                               \
        "mma.sync.aligned.m16n8k8.row.col.f32.tf32.tf32.f32 "                   \
        "{%0,%1,%2,%3}, {%4,%5,%6,%7}, {%8,%9}, {%0,%1,%2,%3};"                 \
        : "+f"((ACC)[0]), "+f"((ACC)[1]), "+f"((ACC)[2]), "+f"((ACC)[3])        \
        : "r"(A0), "r"(A1), "r"(A2), "r"(A3), "r"(B0), "r"(B1))

template <bool HASBIAS, bool RELU, bool DOTS, bool GATHER, bool SPLITK>
__global__ __launch_bounds__(256, 2)
void mma_gemm_kernel(const float* __restrict__ A, const float* __restrict__ B,
                     const float* __restrict__ bias,
                     const float* __restrict__ al, const float* __restrict__ ar,
                     const int* __restrict__ hidx,
                     float* __restrict__ C,
                     float* __restrict__ el, float* __restrict__ er,
                     int M, int K) {
    constexpr int BM = 128, BN = 128, BK = 16;
    __shared__ float AsH[BM * BK];
    __shared__ float AsL[BM * BK];
    __shared__ float BsH[BK * 132];
    __shared__ float BsL[BK * 132];
    __shared__ float sPL[128], sPR[128];

    int t = threadIdx.x;
    int lane = t & 31;
    int warp = t >> 5;
    int warp_m = warp >> 1;   // 0..3
    int warp_n = warp & 1;    // 0..1
    int m_block = blockIdx.x * BM;

    // per-thread load descriptors (fixed across k-iterations)
    const float* arow[2];
    int asw[2], akv[2];
#pragma unroll
    for (int j = 0; j < 2; j++) {
        int idx = t + j * 256;
        int m = idx >> 2;
        int kv = idx & 3;
        if constexpr (GATHER)
            arow[j] = A + (size_t)hidx[m_block + m] * 128;
        else
            arow[j] = A + (size_t)(m_block + m) * K;
        akv[j] = kv * 4;
        asw[j] = m * 16 + (kv ^ (m & 3)) * 4;
    }
    const float* brow[2];
    int bsw[2];
#pragma unroll
    for (int j = 0; j < 2; j++) {
        int idx = t + j * 256;
        int k = idx >> 5;
        int nv = idx & 31;
        brow[j] = B + (size_t)k * BN + nv * 4;
        bsw[j] = k * 132 + nv * 4;
    }

    float acc[2][8][4];
#pragma unroll
    for (int mi = 0; mi < 2; mi++)
#pragma unroll
        for (int ni = 0; ni < 8; ni++)
#pragma unroll
            for (int c = 0; c < 4; c++) acc[mi][ni][c] = 0.f;

    int kstart = SPLITK ? blockIdx.y * 128 : 0;
    int kend   = SPLITK ? kstart + 128 : K;

    float4 ra[2], rb[2];   // staged raw tile

    auto LOAD = [&](int k0) {
#pragma unroll
        for (int j = 0; j < 2; j++) {
            float4 v = *reinterpret_cast<const float4*>(arow[j] + k0 + akv[j]);
            if constexpr (GATHER) {
                v.x = fmaxf(v.x, 0.f); v.y = fmaxf(v.y, 0.f);
                v.z = fmaxf(v.z, 0.f); v.w = fmaxf(v.w, 0.f);
            }
            ra[j] = v;
            rb[j] = *reinterpret_cast<const float4*>(brow[j] + (size_t)k0 * BN);
        }
    };
    auto STORE = [&]() {
#pragma unroll
        for (int j = 0; j < 2; j++) {
            float4 v = ra[j], hi, lo;
            hi.x = tf32r(v.x); lo.x = tf32r(v.x - hi.x);
            hi.y = tf32r(v.y); lo.y = tf32r(v.y - hi.y);
            hi.z = tf32r(v.z); lo.z = tf32r(v.z - hi.z);
            hi.w = tf32r(v.w); lo.w = tf32r(v.w - hi.w);
            *reinterpret_cast<float4*>(AsH + asw[j]) = hi;
            *reinterpret_cast<float4*>(AsL + asw[j]) = lo;
            v = rb[j];
            hi.x = tf32r(v.x); lo.x = tf32r(v.x - hi.x);
            hi.y = tf32r(v.y); lo.y = tf32r(v.y - hi.y);
            hi.z = tf32r(v.z); lo.z = tf32r(v.z - hi.z);
            hi.w = tf32r(v.w); lo.w = tf32r(v.w - hi.w);
            *reinterpret_cast<float4*>(BsH + bsw[j]) = hi;
            *reinterpret_cast<float4*>(BsL + bsw[j]) = lo;
        }
    };

    LOAD(kstart);
    STORE();
    __syncthreads();

    for (int k0 = kstart; k0 < kend; k0 += BK) {
        bool has_next = (k0 + BK) < kend;
        if (has_next) LOAD(k0 + BK);   // overlap LDG latency with MMAs below

#pragma unroll
        for (int kk = 0; kk < 2; kk++) {
            int kc = kk * 8 + (lane & 3);
            unsigned aH[2][4], aL[2][4];
#pragma unroll
            for (int mi = 0; mi < 2; mi++) {
                int r0 = warp_m * 32 + mi * 16 + (lane >> 2);
                int r1 = r0 + 8;
                int i00 = As_idx(r0, kc), i10 = As_idx(r1, kc);
                int i01 = As_idx(r0, kc + 4), i11 = As_idx(r1, kc + 4);
                aH[mi][0] = __float_as_uint(AsH[i00]);
                aH[mi][1] = __float_as_uint(AsH[i10]);
                aH[mi][2] = __float_as_uint(AsH[i01]);
                aH[mi][3] = __float_as_uint(AsH[i11]);
                aL[mi][0] = __float_as_uint(AsL[i00]);
                aL[mi][1] = __float_as_uint(AsL[i10]);
                aL[mi][2] = __float_as_uint(AsL[i01]);
                aL[mi][3] = __float_as_uint(AsL[i11]);
            }
#pragma unroll
            for (int ni = 0; ni < 8; ni++) {
                int nn = warp_n * 64 + ni * 8 + (lane >> 2);
                unsigned bH0 = __float_as_uint(BsH[kc * 132 + nn]);
                unsigned bH1 = __float_as_uint(BsH[(kc + 4) * 132 + nn]);
                unsigned bL0 = __float_as_uint(BsL[kc * 132 + nn]);
                unsigned bL1 = __float_as_uint(BsL[(kc + 4) * 132 + nn]);
#pragma unroll
                for (int mi = 0; mi < 2; mi++) {
                    MMA_TF32(acc[mi][ni], aL[mi][0], aL[mi][1], aL[mi][2], aL[mi][3], bH0, bH1);
                    MMA_TF32(acc[mi][ni], aH[mi][0], aH[mi][1], aH[mi][2], aH[mi][3], bL0, bL1);
                    MMA_TF32(acc[mi][ni], aH[mi][0], aH[mi][1], aH[mi][2], aH[mi][3], bH0, bH1);
                }
            }
        }
        __syncthreads();
        if (has_next) {
            STORE();
            __syncthreads();
        }
    }

    // ---- epilogue: store C ----
#pragma unroll
    for (int mi = 0; mi < 2; mi++) {
        int r = m_block + warp_m * 32 + mi * 16 + (lane >> 2);
#pragma unroll
        for (int ni = 0; ni < 8; ni++) {
            int c = warp_n * 64 + ni * 8 + 2 * (lane & 3);
            float v0 = acc[mi][ni][0], v1 = acc[mi][ni][1];
            float v2 = acc[mi][ni][2], v3 = acc[mi][ni][3];
            if constexpr (SPLITK) {
                atomicAdd(C + (size_t)r * BN + c, v0);
                atomicAdd(C + (size_t)r * BN + c + 1, v1);
                atomicAdd(C + (size_t)(r + 8) * BN + c, v2);
                atomicAdd(C + (size_t)(r + 8) * BN + c + 1, v3);
            } else {
                if (HASBIAS) {
                    float b0 = bias[c], b1 = bias[c + 1];
                    v0 += b0; v1 += b1; v2 += b0; v3 += b1;
                }
                if (RELU) {
                    v0 = fmaxf(v0, 0.f); v1 = fmaxf(v1, 0.f);
                    v2 = fmaxf(v2, 0.f); v3 = fmaxf(v3, 0.f);
                }
                *reinterpret_cast<float2*>(C + (size_t)r * BN + c) = make_float2(v0, v1);
                *reinterpret_cast<float2*>(C + (size_t)(r + 8) * BN + c) = make_float2(v2, v3);
            }
        }
    }

    // ---- fused attention dots ----
    if constexpr (DOTS) {
        float qpl[2][2], qpr[2][2];
#pragma unroll
        for (int mi = 0; mi < 2; mi++) {
            float pl0 = 0.f, pr0 = 0.f, pl1 = 0.f, pr1 = 0.f;
#pragma unroll
            for (int ni = 0; ni < 8; ni++) {
                int c = warp_n * 64 + ni * 8 + 2 * (lane & 3);
                float a0 = al[c], a1 = al[c + 1];
                float g0 = ar[c], g1 = ar[c + 1];
                pl0 += acc[mi][ni][0] * a0 + acc[mi][ni][1] * a1;
                pr0 += acc[mi][ni][0] * g0 + acc[mi][ni][1] * g1;
                pl1 += acc[mi][ni][2] * a0 + acc[mi][ni][3] * a1;
                pr1 += acc[mi][ni][2] * g0 + acc[mi][ni][3] * g1;
            }
#pragma unroll
            for (int o = 1; o <= 2; o <<= 1) {
                pl0 += __shfl_xor_sync(0xffffffffu, pl0, o);
                pr0 += __shfl_xor_sync(0xffffffffu, pr0, o);
                pl1 += __shfl_xor_sync(0xffffffffu, pl1, o);
                pr1 += __shfl_xor_sync(0xffffffffu, pr1, o);
            }
            qpl[mi][0] = pl0; qpl[mi][1] = pl1;
            qpr[mi][0] = pr0; qpr[mi][1] = pr1;
        }
        if ((lane & 3) == 0 && warp_n == 0) {
#pragma unroll
            for (int mi = 0; mi < 2; mi++) {
                int lr = warp_m * 32 + mi * 16 + (lane >> 2);
                sPL[lr] = qpl[mi][0]; sPR[lr] = qpr[mi][0];
                sPL[lr + 8] = qpl[mi][1]; sPR[lr + 8] = qpr[mi][1];
            }
        }
        __syncthreads();
        if ((lane & 3) == 0 && warp_n == 1) {
#pragma unroll
            for (int mi = 0; mi < 2; mi++) {
                int lr = warp_m * 32 + mi * 16 + (lane >> 2);
                el[m_block + lr] = sPL[lr] + qpl[mi][0];
                er[m_block + lr] = sPR[lr] + qpr[mi][0];
                el[m_block + lr + 8] = sPL[lr + 8] + qpl[mi][1];
                er[m_block + lr + 8] = sPR[lr + 8] + qpr[mi][1];
            }
        }
    }
}

// ---------------- small dots (outer graph only) ----------------
__global__ void dots_kernel(const float* __restrict__ f,
                            const float* __restrict__ al,
                            const float* __restrict__ ar,
                            float* __restrict__ el, float* __restrict__ er, int n) {
    int node = blockIdx.x * (blockDim.x >> 5) + (threadIdx.x >> 5);
    int lane = threadIdx.x & 31;
    if (node >= n) return;
    float4 v = reinterpret_cast<const float4*>(f)[(size_t)node * 32 + lane];
    float4 a = reinterpret_cast<const float4*>(al)[lane];
    float4 r = reinterpret_cast<const float4*>(ar)[lane];
    float pl = v.x * a.x + v.y * a.y + v.z * a.z + v.w * a.w;
    float pr = v.x * r.x + v.y * r.y + v.z * r.z + v.w * r.w;
#pragma unroll
    for (int o = 16; o > 0; o >>= 1) {
        pl += __shfl_xor_sync(0xffffffffu, pl, o);
        pr += __shfl_xor_sync(0xffffffffu, pr, o);
    }
    if (lane == 0) {
        el[node] = pl;
        er[node] = pr;
    }
}

// ---------------- fused GAT aggregation (warp per dst node, CSR, x4 unroll) ----------------
__global__ void gat_aggregate_kernel(const int* __restrict__ row_ptr,
                                     const int* __restrict__ col,
                                     const float* __restrict__ el,
                                     const float* __restrict__ er,
                                     const float* __restrict__ f,
                                     const float* __restrict__ b,
                                     float* __restrict__ outx, int n) {
    int node = blockIdx.x * (blockDim.x >> 5) + (threadIdx.x >> 5);
    int lane = threadIdx.x & 31;
    if (node >= n) return;
    int s0 = row_ptr[node];
    int s1 = row_ptr[node + 1];
    float er_i = er[node];
    const float4* f4 = reinterpret_cast<const float4*>(f);
    float4 acc = {0.f, 0.f, 0.f, 0.f};
    float ssum = 0.f;

    int j = s0;
    for (; j + 4 <= s1; j += 4) {
        int sA = col[j], sB = col[j + 1], sC = col[j + 2], sD = col[j + 3];
        float eA = el[sA] + er_i, eB = el[sB] + er_i;
        float eC = el[sC] + er_i, eD = el[sD] + er_i;
        float4 vA = f4[(size_t)sA * 32 + lane];
        float4 vB = f4[(size_t)sB * 32 + lane];
        float4 vC = f4[(size_t)sC * 32 + lane];
        float4 vD = f4[(size_t)sD * 32 + lane];
        eA = eA > 0.f ? eA : 0.2f * eA;  float aA = expf(eA);
        eB = eB > 0.f ? eB : 0.2f * eB;  float aB = expf(eB);
        eC = eC > 0.f ? eC : 0.2f * eC;  float aC = expf(eC);
        eD = eD > 0.f ? eD : 0.2f * eD;  float aD = expf(eD);
        ssum += (aA + aB) + (aC + aD);
        acc.x += aA * vA.x + aB * vB.x + aC * vC.x + aD * vD.x;
        acc.y += aA * vA.y + aB * vB.y + aC * vC.y + aD * vD.y;
        acc.z += aA * vA.z + aB * vB.z + aC * vC.z + aD * vD.z;
        acc.w += aA * vA.w + aB * vB.w + aC * vC.w + aD * vD.w;
    }
    for (; j < s1; j++) {
        int s = col[j];
        float e = el[s] + er_i;
        e = e > 0.f ? e : 0.2f * e;
        float a = expf(e);
        ssum += a;
        float4 v = f4[(size_t)s * 32 + lane];
        acc.x += a * v.x;
        acc.y += a * v.y;
        acc.z += a * v.z;
        acc.w += a * v.w;
    }

    float inv = (s1 > s0) ? 1.f / ssum : 0.f;
    int k = lane * 4;
    float4 o;
    o.x = fmaxf(acc.x * inv + b[k + 0], 0.f);
    o.y = fmaxf(acc.y * inv + b[k + 1], 0.f);
    o.z = fmaxf(acc.z * inv + b[k + 2], 0.f);
    o.w = fmaxf(acc.w * inv + b[k + 3], 0.f);
    reinterpret_cast<float4*>(outx)[(size_t)node * 32 + lane] = o;
}

// ---------------- SortPooling ----------------
__global__ void sortpool_kernel(const float* __restrict__ x, float* __restrict__ y) {
    int g = blockIdx.x;
    __shared__ float mx[64];
    __shared__ int sel[8];
    __shared__ float buf[8][128];
    int t = threadIdx.x;
    int w = t >> 5;
    int lane = t & 31;
    const float* xg = x + (size_t)g * 64 * D_;

#pragma unroll
    for (int it = 0; it < 8; it++) {
        int j = w * 8 + it;
        float4 v = reinterpret_cast<const float4*>(xg + (size_t)j * D_)[lane];
        float m = fmaxf(fmaxf(v.x, v.y), fmaxf(v.z, v.w));
#pragma unroll
        for (int o = 16; o > 0; o >>= 1)
            m = fmaxf(m, __shfl_xor_sync(0xffffffffu, m, o));
        if (lane == 0) mx[j] = m;
    }
    __syncthreads();

    if (t < 64) {
        float mj = mx[t];
        int rank = 0;
        for (int i = 0; i < 64; i++) {
            float mi = mx[i];
            rank += (mi > mj) || (mi == mj && i < t);
        }
        if (rank < 8) sel[rank] = t;
    }
    __syncthreads();

    int j = sel[w];
    reinterpret_cast<float4*>(buf[w])[lane] =
        reinterpret_cast<const float4*>(xg + (size_t)j * D_)[lane];
    __syncwarp();
    for (int k2 = 2; k2 <= 128; k2 <<= 1) {
        for (int jj = k2 >> 1; jj > 0; jj >>= 1) {
#pragma unroll
            for (int base = 0; base < 128; base += 32) {
                int i = base + lane;
                int p = i ^ jj;
                if (p > i) {
                    float a = buf[w][i];
                    float bb = buf[w][p];
                    bool up = (i & k2) == 0;
                    if ((a > bb) == up) {
                        buf[w][i] = bb;
                        buf[w][p] = a;
                    }
                }
            }
            __syncwarp();
        }
    }
    reinterpret_cast<float4*>(y + (size_t)g * (K_ * D_) + w * D_)[lane] =
        reinterpret_cast<float4*>(buf[w])[lane];
}

// ---------------- classifier ----------------
__global__ void classifier_kernel(const float* __restrict__ x,
                                  const float* __restrict__ Wc,
                                  const float* __restrict__ bc,
                                  float* __restrict__ out) {
    int row = (blockIdx.x * blockDim.x + threadIdx.x) >> 5;
    int lane = threadIdx.x & 31;
    if (row >= G_) return;
    float4 v = reinterpret_cast<const float4*>(x + (size_t)row * D_)[lane];
    int k = lane * 4;
    float a0 = v.x * Wc[(k + 0) * 2 + 0] + v.y * Wc[(k + 1) * 2 + 0] +
               v.z * Wc[(k + 2) * 2 + 0] + v.w * Wc[(k + 3) * 2 + 0];
    float a1 = v.x * Wc[(k + 0) * 2 + 1] + v.y * Wc[(k + 1) * 2 + 1] +
               v.z * Wc[(k + 2) * 2 + 1] + v.w * Wc[(k + 3) * 2 + 1];
#pragma unroll
    for (int o = 16; o > 0; o >>= 1) {
        a0 += __shfl_xor_sync(0xffffffffu, a0, o);
        a1 += __shfl_xor_sync(0xffffffffu, a1, o);
    }
    if (lane == 0) {
        out[row * 2 + 0] = a0 + bc[0];
        out[row * 2 + 1] = a1 + bc[1];
    }
}

// ---------------- launch ----------------
extern "C" void kernel_launch(void* const* d_in, const int* in_sizes, int n_in,
                              void* d_out, int out_size) {
    const int*   h      = (const int*)d_in[0];
    const int*   gsrc   = (const int*)d_in[1];
    const int*   gdst   = (const int*)d_in[2];
    const int*   fgsrc  = (const int*)d_in[3];
    const int*   fgdst  = (const int*)d_in[4];
    const float* emb    = (const float*)d_in[5];
    const float* W1  = (const float*)d_in[6];
    const float* al1 = (const float*)d_in[7];
    const float* ar1 = (const float*)d_in[8];
    const float* b1  = (const float*)d_in[9];
    const float* W2  = (const float*)d_in[10];
    const float* al2 = (const float*)d_in[11];
    const float* ar2 = (const float*)d_in[12];
    const float* b2  = (const float*)d_in[13];
    const float* W3  = (const float*)d_in[14];
    const float* al3 = (const float*)d_in[15];
    const float* ar3 = (const float*)d_in[16];
    const float* b3  = (const float*)d_in[17];
    const float* Wf  = (const float*)d_in[18];
    const float* bf  = (const float*)d_in[19];
    const float* Wl  = (const float*)d_in[20];
    const float* bl  = (const float*)d_in[21];
    const float* Wl1 = (const float*)d_in[22];
    const float* bl1 = (const float*)d_in[23];
    const float* Wc  = (const float*)d_in[24];
    const float* bc  = (const float*)d_in[25];
    float* out = (float*)d_out;

    float *gx, *gf, *gel, *ger, *pool;
    float *hf, *hx, *hy, *hel, *her;
    int *cnt, *rowptr, *cursor, *col, *bsum;
    cudaGetSymbolAddress((void**)&gx,  d_gx);
    cudaGetSymbolAddress((void**)&gf,  d_gf);
    cudaGetSymbolAddress((void**)&gel, d_gel);
    cudaGetSymbolAddress((void**)&ger, d_ger);
    cudaGetSymbolAddress((void**)&pool, d_pool);
    cudaGetSymbolAddress((void**)&hf,  d_hf);
    cudaGetSymbolAddress((void**)&hx,  d_hx);
    cudaGetSymbolAddress((void**)&hy,  d_hy);
    cudaGetSymbolAddress((void**)&hel, d_hel);
    cudaGetSymbolAddress((void**)&her, d_her);
    cudaGetSymbolAddress((void**)&cnt,    d_cnt);
    cudaGetSymbolAddress((void**)&rowptr, d_rowptr);
    cudaGetSymbolAddress((void**)&cursor, d_cursor);
    cudaGetSymbolAddress((void**)&col,    d_col);
    cudaGetSymbolAddress((void**)&bsum,   d_bsum);

    // ---- combined CSR build (inner + outer in one pass) ----
    {
        int scanBlocks = (NODES_ALL + 1023) / 1024;   // 130
        zero_int_kernel<<<(NODES_ALL + 255) / 256, 256>>>(cnt, NODES_ALL);
        hist2_kernel<<<(EDGES_ALL + 255) / 256, 256>>>(gdst, fgdst, cnt);
        block_reduce_kernel<<<scanBlocks, 256>>>(cnt, NODES_ALL, bsum);
        scan_small_kernel<<<1, 256>>>(bsum, scanBlocks);
        block_scan_kernel<<<scanBlocks, 256>>>(cnt, NODES_ALL, bsum, rowptr, cursor);
        scatter2_kernel<<<(EDGES_ALL + 255) / 256, 256>>>(gsrc, gdst, fgsrc, fgdst, cursor, col);
    }

    // ---- inner GATConv 1 (embed fused into A-loader, dots fused in epilogue) ----
    mma_gemm_kernel<false, false, true, true, false><<<N_ / 128, 256>>>(
        emb, W1, nullptr, al1, ar1, h, gf, gel, ger, N_, 128);
    gat_aggregate_kernel<<<N_ / 8, 256>>>(rowptr, col, gel, ger, gf, b1, gx, N_);

    // ---- inner GATConv 2 ----
    mma_gemm_kernel<false, false, true, false, false><<<N_ / 128, 256>>>(
        gx, W2, nullptr, al2, ar2, nullptr, gf, gel, ger, N_, 128);
    gat_aggregate_kernel<<<N_ / 8, 256>>>(rowptr, col, gel, ger, gf, b2, gx, N_);

    // linear_forward: f = relu(x @ Wf + bf)
    mma_gemm_kernel<true, true, false, false, false><<<N_ / 128, 256>>>(
        gx, Wf, bf, nullptr, nullptr, nullptr, gf, nullptr, nullptr, N_, 128);

    // sort pooling -> pool [2048, 1024]
    sortpool_kernel<<<G_, 256>>>(gf, pool);

    // ---- outer GATConv over fg (split-K GEMM: 16 x 8 blocks) ----
    zero_float_kernel<<<(G_ * D_ + 255) / 256, 256>>>(hf, G_ * D_);
    {
        dim3 grid(G_ / 128, 8);
        mma_gemm_kernel<false, false, false, false, true><<<grid, 256>>>(
            pool, W3, nullptr, nullptr, nullptr, nullptr, hf, nullptr, nullptr, G_, 1024);
    }
    dots_kernel<<<G_ / 8, 256>>>(hf, al3, ar3, hel, her, G_);
    gat_aggregate_kernel<<<G_ / 8, 256>>>(rowptr + N_, col, hel, her, hf, b3, hx, G_);

    // x = relu(x @ Wl + bl); x = relu(x @ Wl1 + bl1)
    mma_gemm_kernel<true, true, false, false, false><<<G_ / 128, 256>>>(
        hx, Wl, bl, nullptr, nullptr, nullptr, hy, nullptr, nullptr, G_, 128);
    mma_gemm_kernel<true, true, false, false, false><<<G_ / 128, 256>>>(
        hy, Wl1, bl1, nullptr, nullptr, nullptr, hx, nullptr, nullptr, G_, 128);

    // classifier
    classifier_kernel<<<(G_ * 32 + 255) / 256, 256>>>(hx, Wc, bc, out);
}

// round 12
// speedup vs baseline: 3.7370x; 1.1918x over previous
#include <cuda_runtime.h>
#include <cstddef>
#include <cstdint>

// ---------------- problem constants ----------------
constexpr int N_  = 131072;   // inner nodes
constexpr int G_  = 2048;     // graphs / outer nodes
constexpr int E_  = 1048576;  // inner edges
constexpr int EF_ = 32768;    // outer edges
constexpr int D_  = 128;      // feature dim
constexpr int K_  = 8;        // sortpool k
constexpr int VOCAB_ = 150;
constexpr int NODES_ALL = N_ + G_;        // combined CSR node space
constexpr int EDGES_ALL = E_ + EF_;       // combined CSR edge space

// ---------------- scratch (static device globals; no allocation) ----------------
__device__ float d_gx[(size_t)N_ * D_];
__device__ float d_gf[(size_t)N_ * D_];
__device__ float d_gel[N_];
__device__ float d_ger[N_];
__device__ float d_pool[(size_t)G_ * K_ * D_];
__device__ float d_hf[G_ * D_];
__device__ float d_hx[G_ * D_];
__device__ float d_hy[G_ * D_];
__device__ float d_hel[G_];
__device__ float d_her[G_];
// conv1 vocab tables (padded to 256 rows)
__device__ float d_ftab[256 * D_];
__device__ float d_eltab[256];
__device__ float d_ertab[256];

// combined CSR scratch (inner graph nodes 0..N_-1, outer at N_..N_+G_-1)
__device__ int d_cnt[NODES_ALL];
__device__ int d_rowptr[NODES_ALL + 1];
__device__ int d_cursor[NODES_ALL];
__device__ int d_col[EDGES_ALL];
__device__ int d_bsum[256];

// ---------------- utility kernels ----------------
__global__ void zero_int_kernel(int* __restrict__ p, int n) {
    int i = blockIdx.x * blockDim.x + threadIdx.x;
    if (i < n) p[i] = 0;
}

__global__ void zero_float_kernel(float* __restrict__ p, int n) {
    int i = blockIdx.x * blockDim.x + threadIdx.x;
    if (i < n) p[i] = 0.f;
}

// ---------------- combined CSR build ----------------
__global__ void hist2_kernel(const int* __restrict__ gdst,
                             const int* __restrict__ fgdst,
                             int* __restrict__ cnt) {
    int e = blockIdx.x * blockDim.x + threadIdx.x;
    if (e < E_) atomicAdd(&cnt[gdst[e]], 1);
    else if (e < EDGES_ALL) atomicAdd(&cnt[N_ + fgdst[e - E_]], 1);
}

__global__ void block_reduce_kernel(const int* __restrict__ cnt, int n,
                                    int* __restrict__ bsum) {
    __shared__ int sh[256];
    int base = blockIdx.x * 1024;
    int t = threadIdx.x;
    int s = 0;
#pragma unroll
    for (int i = 0; i < 4; i++) {
        int idx = base + t * 4 + i;
        if (idx < n) s += cnt[idx];
    }
    sh[t] = s;
    __syncthreads();
    for (int o = 128; o > 0; o >>= 1) {
        if (t < o) sh[t] += sh[t + o];
        __syncthreads();
    }
    if (t == 0) bsum[blockIdx.x] = sh[0];
}

__global__ void scan_small_kernel(int* __restrict__ bsum, int nb) {
    __shared__ int sh[256];
    int t = threadIdx.x;
    int orig = t < nb ? bsum[t] : 0;
    sh[t] = orig;
    __syncthreads();
    for (int o = 1; o < 256; o <<= 1) {
        int u = t >= o ? sh[t - o] : 0;
        __syncthreads();
        sh[t] += u;
        __syncthreads();
    }
    if (t < nb) bsum[t] = sh[t] - orig;
}

__global__ void block_scan_kernel(const int* __restrict__ cnt, int n,
                                  const int* __restrict__ bsum,
                                  int* __restrict__ row_ptr,
                                  int* __restrict__ cursor) {
    __shared__ int sh[256];
    int base = blockIdx.x * 1024;
    int t = threadIdx.x;
    int v[4];
    int s = 0;
#pragma unroll
    for (int i = 0; i < 4; i++) {
        int idx = base + t * 4 + i;
        v[i] = idx < n ? cnt[idx] : 0;
        s += v[i];
    }
    sh[t] = s;
    __syncthreads();
    for (int o = 1; o < 256; o <<= 1) {
        int u = t >= o ? sh[t - o] : 0;
        __syncthreads();
        sh[t] += u;
        __syncthreads();
    }
    int off = bsum[blockIdx.x] + (t > 0 ? sh[t - 1] : 0);
#pragma unroll
    for (int i = 0; i < 4; i++) {
        int idx = base + t * 4 + i;
        if (idx < n) {
            row_ptr[idx] = off;
            cursor[idx] = off;
            off += v[i];
            if (idx == n - 1) row_ptr[n] = off;
        }
    }
}

__global__ void scatter2_kernel(const int* __restrict__ gsrc, const int* __restrict__ gdst,
                                const int* __restrict__ fgsrc, const int* __restrict__ fgdst,
                                int* __restrict__ cursor, int* __restrict__ col) {
    int e = blockIdx.x * blockDim.x + threadIdx.x;
    if (e < E_) {
        int pos = atomicAdd(&cursor[gdst[e]], 1);
        col[pos] = gsrc[e];
    } else if (e < EDGES_ALL) {
        int ef = e - E_;
        int pos = atomicAdd(&cursor[N_ + fgdst[ef]], 1);
        col[pos] = fgsrc[ef];
    }
}

// ---------------- 3xTF32 MMA GEMM (software-pipelined) ----------------
// C[M,128] = act(A[M,K] @ B[K,128] (+bias))
// GMODE: 0 = plain rows; 2 = vocab-clamped row with relu (A row m is relu(A[min(m,149)]))
// DOTS:   also emit el[m]=C_row.al, er[m]=C_row.ar (pre-activation C)
// SPLITK: gridDim.y k-chunks of 128; epilogue atomicAdd into C
__device__ __forceinline__ float tf32r(float x) {
    unsigned u;
    asm("cvt.rna.tf32.f32 %0, %1;" : "=r"(u) : "f"(x));
    return __uint_as_float(u);
}

__device__ __forceinline__ int As_idx(int m, int k) {
    return m * 16 + ((((k >> 2) ^ (m & 3)) << 2) | (k & 3));
}

#define MMA_TF32(ACC, A0, A1, A2, A3, B0, B1)                                   \
    asm volatile(                                                               \
        "mma.sync.aligned.m16n8k8.row.col.f32.tf32.tf32.f32 "                   \
        "{%0,%1,%2,%3}, {%4,%5,%6,%7}, {%8,%9}, {%0,%1,%2,%3};"                 \
        : "+f"((ACC)[0]), "+f"((ACC)[1]), "+f"((ACC)[2]), "+f"((ACC)[3])        \
        : "r"(A0), "r"(A1), "r"(A2), "r"(A3), "r"(B0), "r"(B1))

template <bool HASBIAS, bool RELU, bool DOTS, int GMODE, bool SPLITK>
__global__ __launch_bounds__(256, 2)
void mma_gemm_kernel(const float* __restrict__ A, const float* __restrict__ B,
                     const float* __restrict__ bias,
                     const float* __restrict__ al, const float* __restrict__ ar,
                     float* __restrict__ C,
                     float* __restrict__ el, float* __restrict__ er,
                     int M, int K) {
    constexpr int BM = 128, BN = 128, BK = 16;
    __shared__ float AsH[BM * BK];
    __shared__ float AsL[BM * BK];
    __shared__ float BsH[BK * 132];
    __shared__ float BsL[BK * 132];
    __shared__ float sPL[128], sPR[128];

    int t = threadIdx.x;
    int lane = t & 31;
    int warp = t >> 5;
    int warp_m = warp >> 1;   // 0..3
    int warp_n = warp & 1;    // 0..1
    int m_block = blockIdx.x * BM;

    // per-thread load descriptors (fixed across k-iterations)
    const float* arow[2];
    int asw[2], akv[2];
#pragma unroll
    for (int j = 0; j < 2; j++) {
        int idx = t + j * 256;
        int m = idx >> 2;
        int kv = idx & 3;
        int mm = m_block + m;
        if constexpr (GMODE == 2)
            arow[j] = A + (size_t)(mm < VOCAB_ ? mm : VOCAB_ - 1) * 128;
        else
            arow[j] = A + (size_t)mm * K;
        akv[j] = kv * 4;
        asw[j] = m * 16 + (kv ^ (m & 3)) * 4;
    }
    const float* brow[2];
    int bsw[2];
#pragma unroll
    for (int j = 0; j < 2; j++) {
        int idx = t + j * 256;
        int k = idx >> 5;
        int nv = idx & 31;
        brow[j] = B + (size_t)k * BN + nv * 4;
        bsw[j] = k * 132 + nv * 4;
    }

    float acc[2][8][4];
#pragma unroll
    for (int mi = 0; mi < 2; mi++)
#pragma unroll
        for (int ni = 0; ni < 8; ni++)
#pragma unroll
            for (int c = 0; c < 4; c++) acc[mi][ni][c] = 0.f;

    int kstart = SPLITK ? blockIdx.y * 128 : 0;
    int kend   = SPLITK ? kstart + 128 : K;

    float4 ra[2], rb[2];   // staged raw tile

    auto LOAD = [&](int k0) {
#pragma unroll
        for (int j = 0; j < 2; j++) {
            float4 v = *reinterpret_cast<const float4*>(arow[j] + k0 + akv[j]);
            if constexpr (GMODE == 2) {
                v.x = fmaxf(v.x, 0.f); v.y = fmaxf(v.y, 0.f);
                v.z = fmaxf(v.z, 0.f); v.w = fmaxf(v.w, 0.f);
            }
            ra[j] = v;
            rb[j] = *reinterpret_cast<const float4*>(brow[j] + (size_t)k0 * BN);
        }
    };
    auto STORE = [&]() {
#pragma unroll
        for (int j = 0; j < 2; j++) {
            float4 v = ra[j], hi, lo;
            hi.x = tf32r(v.x); lo.x = tf32r(v.x - hi.x);
            hi.y = tf32r(v.y); lo.y = tf32r(v.y - hi.y);
            hi.z = tf32r(v.z); lo.z = tf32r(v.z - hi.z);
            hi.w = tf32r(v.w); lo.w = tf32r(v.w - hi.w);
            *reinterpret_cast<float4*>(AsH + asw[j]) = hi;
            *reinterpret_cast<float4*>(AsL + asw[j]) = lo;
            v = rb[j];
            hi.x = tf32r(v.x); lo.x = tf32r(v.x - hi.x);
            hi.y = tf32r(v.y); lo.y = tf32r(v.y - hi.y);
            hi.z = tf32r(v.z); lo.z = tf32r(v.z - hi.z);
            hi.w = tf32r(v.w); lo.w = tf32r(v.w - hi.w);
            *reinterpret_cast<float4*>(BsH + bsw[j]) = hi;
            *reinterpret_cast<float4*>(BsL + bsw[j]) = lo;
        }
    };

    LOAD(kstart);
    STORE();
    __syncthreads();

    for (int k0 = kstart; k0 < kend; k0 += BK) {
        bool has_next = (k0 + BK) < kend;
        if (has_next) LOAD(k0 + BK);   // overlap LDG latency with MMAs below

#pragma unroll
        for (int kk = 0; kk < 2; kk++) {
            int kc = kk * 8 + (lane & 3);
            unsigned aH[2][4], aL[2][4];
#pragma unroll
            for (int mi = 0; mi < 2; mi++) {
                int r0 = warp_m * 32 + mi * 16 + (lane >> 2);
                int r1 = r0 + 8;
                int i00 = As_idx(r0, kc), i10 = As_idx(r1, kc);
                int i01 = As_idx(r0, kc + 4), i11 = As_idx(r1, kc + 4);
                aH[mi][0] = __float_as_uint(AsH[i00]);
                aH[mi][1] = __float_as_uint(AsH[i10]);
                aH[mi][2] = __float_as_uint(AsH[i01]);
                aH[mi][3] = __float_as_uint(AsH[i11]);
                aL[mi][0] = __float_as_uint(AsL[i00]);
                aL[mi][1] = __float_as_uint(AsL[i10]);
                aL[mi][2] = __float_as_uint(AsL[i01]);
                aL[mi][3] = __float_as_uint(AsL[i11]);
            }
#pragma unroll
            for (int ni = 0; ni < 8; ni++) {
                int nn = warp_n * 64 + ni * 8 + (lane >> 2);
                unsigned bH0 = __float_as_uint(BsH[kc * 132 + nn]);
                unsigned bH1 = __float_as_uint(BsH[(kc + 4) * 132 + nn]);
                unsigned bL0 = __float_as_uint(BsL[kc * 132 + nn]);
                unsigned bL1 = __float_as_uint(BsL[(kc + 4) * 132 + nn]);
#pragma unroll
                for (int mi = 0; mi < 2; mi++) {
                    MMA_TF32(acc[mi][ni], aL[mi][0], aL[mi][1], aL[mi][2], aL[mi][3], bH0, bH1);
                    MMA_TF32(acc[mi][ni], aH[mi][0], aH[mi][1], aH[mi][2], aH[mi][3], bL0, bL1);
                    MMA_TF32(acc[mi][ni], aH[mi][0], aH[mi][1], aH[mi][2], aH[mi][3], bH0, bH1);
                }
            }
        }
        __syncthreads();
        if (has_next) {
            STORE();
            __syncthreads();
        }
    }

    // ---- epilogue: store C ----
#pragma unroll
    for (int mi = 0; mi < 2; mi++) {
        int r = m_block + warp_m * 32 + mi * 16 + (lane >> 2);
#pragma unroll
        for (int ni = 0; ni < 8; ni++) {
            int c = warp_n * 64 + ni * 8 + 2 * (lane & 3);
            float v0 = acc[mi][ni][0], v1 = acc[mi][ni][1];
            float v2 = acc[mi][ni][2], v3 = acc[mi][ni][3];
            if constexpr (SPLITK) {
                atomicAdd(C + (size_t)r * BN + c, v0);
                atomicAdd(C + (size_t)r * BN + c + 1, v1);
                atomicAdd(C + (size_t)(r + 8) * BN + c, v2);
                atomicAdd(C + (size_t)(r + 8) * BN + c + 1, v3);
            } else {
                if (HASBIAS) {
                    float b0 = bias[c], b1 = bias[c + 1];
                    v0 += b0; v1 += b1; v2 += b0; v3 += b1;
                }
                if (RELU) {
                    v0 = fmaxf(v0, 0.f); v1 = fmaxf(v1, 0.f);
                    v2 = fmaxf(v2, 0.f); v3 = fmaxf(v3, 0.f);
                }
                *reinterpret_cast<float2*>(C + (size_t)r * BN + c) = make_float2(v0, v1);
                *reinterpret_cast<float2*>(C + (size_t)(r + 8) * BN + c) = make_float2(v2, v3);
            }
        }
    }

    // ---- fused attention dots ----
    if constexpr (DOTS) {
        float qpl[2][2], qpr[2][2];
#pragma unroll
        for (int mi = 0; mi < 2; mi++) {
            float pl0 = 0.f, pr0 = 0.f, pl1 = 0.f, pr1 = 0.f;
#pragma unroll
            for (int ni = 0; ni < 8; ni++) {
                int c = warp_n * 64 + ni * 8 + 2 * (lane & 3);
                float a0 = al[c], a1 = al[c + 1];
                float g0 = ar[c], g1 = ar[c + 1];
                pl0 += acc[mi][ni][0] * a0 + acc[mi][ni][1] * a1;
                pr0 += acc[mi][ni][0] * g0 + acc[mi][ni][1] * g1;
                pl1 += acc[mi][ni][2] * a0 + acc[mi][ni][3] * a1;
                pr1 += acc[mi][ni][2] * g0 + acc[mi][ni][3] * g1;
            }
#pragma unroll
            for (int o = 1; o <= 2; o <<= 1) {
                pl0 += __shfl_xor_sync(0xffffffffu, pl0, o);
                pr0 += __shfl_xor_sync(0xffffffffu, pr0, o);
                pl1 += __shfl_xor_sync(0xffffffffu, pl1, o);
                pr1 += __shfl_xor_sync(0xffffffffu, pr1, o);
            }
            qpl[mi][0] = pl0; qpl[mi][1] = pl1;
            qpr[mi][0] = pr0; qpr[mi][1] = pr1;
        }
        if ((lane & 3) == 0 && warp_n == 0) {
#pragma unroll
            for (int mi = 0; mi < 2; mi++) {
                int lr = warp_m * 32 + mi * 16 + (lane >> 2);
                sPL[lr] = qpl[mi][0]; sPR[lr] = qpr[mi][0];
                sPL[lr + 8] = qpl[mi][1]; sPR[lr + 8] = qpr[mi][1];
            }
        }
        __syncthreads();
        if ((lane & 3) == 0 && warp_n == 1) {
#pragma unroll
            for (int mi = 0; mi < 2; mi++) {
                int lr = warp_m * 32 + mi * 16 + (lane >> 2);
                el[m_block + lr] = sPL[lr] + qpl[mi][0];
                er[m_block + lr] = sPR[lr] + qpr[mi][0];
                el[m_block + lr + 8] = sPL[lr + 8] + qpl[mi][1];
                er[m_block + lr + 8] = sPR[lr + 8] + qpr[mi][1];
            }
        }
    }
}

// ---------------- small dots (outer graph only) ----------------
__global__ void dots_kernel(const float* __restrict__ f,
                            const float* __restrict__ al,
                            const float* __restrict__ ar,
                            float* __restrict__ el, float* __restrict__ er, int n) {
    int node = blockIdx.x * (blockDim.x >> 5) + (threadIdx.x >> 5);
    int lane = threadIdx.x & 31;
    if (node >= n) return;
    float4 v = reinterpret_cast<const float4*>(f)[(size_t)node * 32 + lane];
    float4 a = reinterpret_cast<const float4*>(al)[lane];
    float4 r = reinterpret_cast<const float4*>(ar)[lane];
    float pl = v.x * a.x + v.y * a.y + v.z * a.z + v.w * a.w;
    float pr = v.x * r.x + v.y * r.y + v.z * r.z + v.w * r.w;
#pragma unroll
    for (int o = 16; o > 0; o >>= 1) {
        pl += __shfl_xor_sync(0xffffffffu, pl, o);
        pr += __shfl_xor_sync(0xffffffffu, pr, o);
    }
    if (lane == 0) {
        el[node] = pl;
        er[node] = pr;
    }
}

// ---------------- fused GAT aggregation (warp per dst node, CSR, x4 unroll) ----------------
__global__ void gat_aggregate_kernel(const int* __restrict__ row_ptr,
                                     const int* __restrict__ col,
                                     const float* __restrict__ el,
                                     const float* __restrict__ er,
                                     const float* __restrict__ f,
                                     const float* __restrict__ b,
                                     float* __restrict__ outx, int n) {
    int node = blockIdx.x * (blockDim.x >> 5) + (threadIdx.x >> 5);
    int lane = threadIdx.x & 31;
    if (node >= n) return;
    int s0 = row_ptr[node];
    int s1 = row_ptr[node + 1];
    float er_i = er[node];
    const float4* f4 = reinterpret_cast<const float4*>(f);
    float4 acc = {0.f, 0.f, 0.f, 0.f};
    float ssum = 0.f;

    int j = s0;
    for (; j + 4 <= s1; j += 4) {
        int sA = col[j], sB = col[j + 1], sC = col[j + 2], sD = col[j + 3];
        float eA = el[sA] + er_i, eB = el[sB] + er_i;
        float eC = el[sC] + er_i, eD = el[sD] + er_i;
        float4 vA = f4[(size_t)sA * 32 + lane];
        float4 vB = f4[(size_t)sB * 32 + lane];
        float4 vC = f4[(size_t)sC * 32 + lane];
        float4 vD = f4[(size_t)sD * 32 + lane];
        eA = eA > 0.f ? eA : 0.2f * eA;  float aA = expf(eA);
        eB = eB > 0.f ? eB : 0.2f * eB;  float aB = expf(eB);
        eC = eC > 0.f ? eC : 0.2f * eC;  float aC = expf(eC);
        eD = eD > 0.f ? eD : 0.2f * eD;  float aD = expf(eD);
        ssum += (aA + aB) + (aC + aD);
        acc.x += aA * vA.x + aB * vB.x + aC * vC.x + aD * vD.x;
        acc.y += aA * vA.y + aB * vB.y + aC * vC.y + aD * vD.y;
        acc.z += aA * vA.z + aB * vB.z + aC * vC.z + aD * vD.z;
        acc.w += aA * vA.w + aB * vB.w + aC * vC.w + aD * vD.w;
    }
    for (; j < s1; j++) {
        int s = col[j];
        float e = el[s] + er_i;
        e = e > 0.f ? e : 0.2f * e;
        float a = expf(e);
        ssum += a;
        float4 v = f4[(size_t)s * 32 + lane];
        acc.x += a * v.x;
        acc.y += a * v.y;
        acc.z += a * v.z;
        acc.w += a * v.w;
    }

    float inv = (s1 > s0) ? 1.f / ssum : 0.f;
    int k = lane * 4;
    float4 o;
    o.x = fmaxf(acc.x * inv + b[k + 0], 0.f);
    o.y = fmaxf(acc.y * inv + b[k + 1], 0.f);
    o.z = fmaxf(acc.z * inv + b[k + 2], 0.f);
    o.w = fmaxf(acc.w * inv + b[k + 3], 0.f);
    reinterpret_cast<float4*>(outx)[(size_t)node * 32 + lane] = o;
}

// ---------------- conv1 aggregation via vocab tables (L1-resident gather) ----------------
// f[src] = ftab[h[src]], el[src] = eltab[h[src]], er[dst] = ertab[h[dst]]
__global__ void gat_aggregate_vocab_kernel(const int* __restrict__ row_ptr,
                                           const int* __restrict__ col,
                                           const int* __restrict__ h,
                                           const float* __restrict__ eltab,
                                           const float* __restrict__ ertab,
                                           const float* __restrict__ ftab,
                                           const float* __restrict__ b,
                                           float* __restrict__ outx, int n) {
    int node = blockIdx.x * (blockDim.x >> 5) + (threadIdx.x >> 5);
    int lane = threadIdx.x & 31;
    if (node >= n) return;
    int s0 = row_ptr[node];
    int s1 = row_ptr[node + 1];
    float er_i = ertab[h[node]];
    const float4* f4 = reinterpret_cast<const float4*>(ftab);
    float4 acc = {0.f, 0.f, 0.f, 0.f};
    float ssum = 0.f;

    int j = s0;
    for (; j + 4 <= s1; j += 4) {
        int hA = h[col[j]], hB = h[col[j + 1]], hC = h[col[j + 2]], hD = h[col[j + 3]];
        float eA = eltab[hA] + er_i, eB = eltab[hB] + er_i;
        float eC = eltab[hC] + er_i, eD = eltab[hD] + er_i;
        float4 vA = f4[(size_t)hA * 32 + lane];
        float4 vB = f4[(size_t)hB * 32 + lane];
        float4 vC = f4[(size_t)hC * 32 + lane];
        float4 vD = f4[(size_t)hD * 32 + lane];
        eA = eA > 0.f ? eA : 0.2f * eA;  float aA = expf(eA);
        eB = eB > 0.f ? eB : 0.2f * eB;  float aB = expf(eB);
        eC = eC > 0.f ? eC : 0.2f * eC;  float aC = expf(eC);
        eD = eD > 0.f ? eD : 0.2f * eD;  float aD = expf(eD);
        ssum += (aA + aB) + (aC + aD);
        acc.x += aA * vA.x + aB * vB.x + aC * vC.x + aD * vD.x;
        acc.y += aA * vA.y + aB * vB.y + aC * vC.y + aD * vD.y;
        acc.z += aA * vA.z + aB * vB.z + aC * vC.z + aD * vD.z;
        acc.w += aA * vA.w + aB * vB.w + aC * vC.w + aD * vD.w;
    }
    for (; j < s1; j++) {
        int hs = h[col[j]];
        float e = eltab[hs] + er_i;
        e = e > 0.f ? e : 0.2f * e;
        float a = expf(e);
        ssum += a;
        float4 v = f4[(size_t)hs * 32 + lane];
        acc.x += a * v.x;
        acc.y += a * v.y;
        acc.z += a * v.z;
        acc.w += a * v.w;
    }

    float inv = (s1 > s0) ? 1.f / ssum : 0.f;
    int k = lane * 4;
    float4 o;
    o.x = fmaxf(acc.x * inv + b[k + 0], 0.f);
    o.y = fmaxf(acc.y * inv + b[k + 1], 0.f);
    o.z = fmaxf(acc.z * inv + b[k + 2], 0.f);
    o.w = fmaxf(acc.w * inv + b[k + 3], 0.f);
    reinterpret_cast<float4*>(outx)[(size_t)node * 32 + lane] = o;
}

// ---------------- SortPooling ----------------
__global__ void sortpool_kernel(const float* __restrict__ x, float* __restrict__ y) {
    int g = blockIdx.x;
    __shared__ float mx[64];
    __shared__ int sel[8];
    __shared__ float buf[8][128];
    int t = threadIdx.x;
    int w = t >> 5;
    int lane = t & 31;
    const float* xg = x + (size_t)g * 64 * D_;

#pragma unroll
    for (int it = 0; it < 8; it++) {
        int j = w * 8 + it;
        float4 v = reinterpret_cast<const float4*>(xg + (size_t)j * D_)[lane];
        float m = fmaxf(fmaxf(v.x, v.y), fmaxf(v.z, v.w));
#pragma unroll
        for (int o = 16; o > 0; o >>= 1)
            m = fmaxf(m, __shfl_xor_sync(0xffffffffu, m, o));
        if (lane == 0) mx[j] = m;
    }
    __syncthreads();

    if (t < 64) {
        float mj = mx[t];
        int rank = 0;
        for (int i = 0; i < 64; i++) {
            float mi = mx[i];
            rank += (mi > mj) || (mi == mj && i < t);
        }
        if (rank < 8) sel[rank] = t;
    }
    __syncthreads();

    int j = sel[w];
    reinterpret_cast<float4*>(buf[w])[lane] =
        reinterpret_cast<const float4*>(xg + (size_t)j * D_)[lane];
    __syncwarp();
    for (int k2 = 2; k2 <= 128; k2 <<= 1) {
        for (int jj = k2 >> 1; jj > 0; jj >>= 1) {
#pragma unroll
            for (int base = 0; base < 128; base += 32) {
                int i = base + lane;
                int p = i ^ jj;
                if (p > i) {
                    float a = buf[w][i];
                    float bb = buf[w][p];
                    bool up = (i & k2) == 0;
                    if ((a > bb) == up) {
                        buf[w][i] = bb;
                        buf[w][p] = a;
                    }
                }
            }
            __syncwarp();
        }
    }
    reinterpret_cast<float4*>(y + (size_t)g * (K_ * D_) + w * D_)[lane] =
        reinterpret_cast<float4*>(buf[w])[lane];
}

// ---------------- classifier ----------------
__global__ void classifier_kernel(const float* __restrict__ x,
                                  const float* __restrict__ Wc,
                                  const float* __restrict__ bc,
                                  float* __restrict__ out) {
    int row = (blockIdx.x * blockDim.x + threadIdx.x) >> 5;
    int lane = threadIdx.x & 31;
    if (row >= G_) return;
    float4 v = reinterpret_cast<const float4*>(x + (size_t)row * D_)[lane];
    int k = lane * 4;
    float a0 = v.x * Wc[(k + 0) * 2 + 0] + v.y * Wc[(k + 1) * 2 + 0] +
               v.z * Wc[(k + 2) * 2 + 0] + v.w * Wc[(k + 3) * 2 + 0];
    float a1 = v.x * Wc[(k + 0) * 2 + 1] + v.y * Wc[(k + 1) * 2 + 1] +
               v.z * Wc[(k + 2) * 2 + 1] + v.w * Wc[(k + 3) * 2 + 1];
#pragma unroll
    for (int o = 16; o > 0; o >>= 1) {
        a0 += __shfl_xor_sync(0xffffffffu, a0, o);
        a1 += __shfl_xor_sync(0xffffffffu, a1, o);
    }
    if (lane == 0) {
        out[row * 2 + 0] = a0 + bc[0];
        out[row * 2 + 1] = a1 + bc[1];
    }
}

// ---------------- launch ----------------
extern "C" void kernel_launch(void* const* d_in, const int* in_sizes, int n_in,
                              void* d_out, int out_size) {
    const int*   h      = (const int*)d_in[0];
    const int*   gsrc   = (const int*)d_in[1];
    const int*   gdst   = (const int*)d_in[2];
    const int*   fgsrc  = (const int*)d_in[3];
    const int*   fgdst  = (const int*)d_in[4];
    const float* emb    = (const float*)d_in[5];
    const float* W1  = (const float*)d_in[6];
    const float* al1 = (const float*)d_in[7];
    const float* ar1 = (const float*)d_in[8];
    const float* b1  = (const float*)d_in[9];
    const float* W2  = (const float*)d_in[10];
    const float* al2 = (const float*)d_in[11];
    const float* ar2 = (const float*)d_in[12];
    const float* b2  = (const float*)d_in[13];
    const float* W3  = (const float*)d_in[14];
    const float* al3 = (const float*)d_in[15];
    const float* ar3 = (const float*)d_in[16];
    const float* b3  = (const float*)d_in[17];
    const float* Wf  = (const float*)d_in[18];
    const float* bf  = (const float*)d_in[19];
    const float* Wl  = (const float*)d_in[20];
    const float* bl  = (const float*)d_in[21];
    const float* Wl1 = (const float*)d_in[22];
    const float* bl1 = (const float*)d_in[23];
    const float* Wc  = (const float*)d_in[24];
    const float* bc  = (const float*)d_in[25];
    float* out = (float*)d_out;

    float *gx, *gf, *gel, *ger, *pool;
    float *hf, *hx, *hy, *hel, *her;
    float *ftab, *eltab, *ertab;
    int *cnt, *rowptr, *cursor, *col, *bsum;
    cudaGetSymbolAddress((void**)&gx,  d_gx);
    cudaGetSymbolAddress((void**)&gf,  d_gf);
    cudaGetSymbolAddress((void**)&gel, d_gel);
    cudaGetSymbolAddress((void**)&ger, d_ger);
    cudaGetSymbolAddress((void**)&pool, d_pool);
    cudaGetSymbolAddress((void**)&hf,  d_hf);
    cudaGetSymbolAddress((void**)&hx,  d_hx);
    cudaGetSymbolAddress((void**)&hy,  d_hy);
    cudaGetSymbolAddress((void**)&hel, d_hel);
    cudaGetSymbolAddress((void**)&her, d_her);
    cudaGetSymbolAddress((void**)&ftab,  d_ftab);
    cudaGetSymbolAddress((void**)&eltab, d_eltab);
    cudaGetSymbolAddress((void**)&ertab, d_ertab);
    cudaGetSymbolAddress((void**)&cnt,    d_cnt);
    cudaGetSymbolAddress((void**)&rowptr, d_rowptr);
    cudaGetSymbolAddress((void**)&cursor, d_cursor);
    cudaGetSymbolAddress((void**)&col,    d_col);
    cudaGetSymbolAddress((void**)&bsum,   d_bsum);

    // ---- combined CSR build (inner + outer in one pass) ----
    {
        int scanBlocks = (NODES_ALL + 1023) / 1024;   // 130
        zero_int_kernel<<<(NODES_ALL + 255) / 256, 256>>>(cnt, NODES_ALL);
        hist2_kernel<<<(EDGES_ALL + 255) / 256, 256>>>(gdst, fgdst, cnt);
        block_reduce_kernel<<<scanBlocks, 256>>>(cnt, NODES_ALL, bsum);
        scan_small_kernel<<<1, 256>>>(bsum, scanBlocks);
        block_scan_kernel<<<scanBlocks, 256>>>(cnt, NODES_ALL, bsum, rowptr, cursor);
        scatter2_kernel<<<(EDGES_ALL + 255) / 256, 256>>>(gsrc, gdst, fgsrc, fgdst, cursor, col);
    }

    // ---- inner GATConv 1 via vocab tables (150 distinct token rows) ----
    // f_tab = relu(emb) @ W1 for all vocab rows (padded to 256), fused el/er tables
    mma_gemm_kernel<false, false, true, 2, false><<<2, 256>>>(
        emb, W1, nullptr, al1, ar1, ftab, eltab, ertab, 256, 128);
    gat_aggregate_vocab_kernel<<<N_ / 8, 256>>>(
        rowptr, col, h, eltab, ertab, ftab, b1, gx, N_);

    // ---- inner GATConv 2 ----
    mma_gemm_kernel<false, false, true, 0, false><<<N_ / 128, 256>>>(
        gx, W2, nullptr, al2, ar2, gf, gel, ger, N_, 128);
    gat_aggregate_kernel<<<N_ / 8, 256>>>(rowptr, col, gel, ger, gf, b2, gx, N_);

    // linear_forward: f = relu(x @ Wf + bf)
    mma_gemm_kernel<true, true, false, 0, false><<<N_ / 128, 256>>>(
        gx, Wf, bf, nullptr, nullptr, gf, nullptr, nullptr, N_, 128);

    // sort pooling -> pool [2048, 1024]
    sortpool_kernel<<<G_, 256>>>(gf, pool);

    // ---- outer GATConv over fg (split-K GEMM: 16 x 8 blocks) ----
    zero_float_kernel<<<(G_ * D_ + 255) / 256, 256>>>(hf, G_ * D_);
    {
        dim3 grid(G_ / 128, 8);
        mma_gemm_kernel<false, false, false, 0, true><<<grid, 256>>>(
            pool, W3, nullptr, nullptr, nullptr, hf, nullptr, nullptr, G_, 1024);
    }
    dots_kernel<<<G_ / 8, 256>>>(hf, al3, ar3, hel, her, G_);
    gat_aggregate_kernel<<<G_ / 8, 256>>>(rowptr + N_, col, hel, her, hf, b3, hx, G_);

    // x = relu(x @ Wl + bl); x = relu(x @ Wl1 + bl1)
    mma_gemm_kernel<true, true, false, 0, false><<<G_ / 128, 256>>>(
        hx, Wl, bl, nullptr, nullptr, hy, nullptr, nullptr, G_, 128);
    mma_gemm_kernel<true, true, false, 0, false><<<G_ / 128, 256>>>(
        hy, Wl1, bl1, nullptr, nullptr, hx, nullptr, nullptr, G_, 128);

    // classifier
    classifier_kernel<<<(G_ * 32 + 255) / 256, 256>>>(hx, Wc, bc, out);
}